// round 5
// baseline (speedup 1.0000x reference)
#include <cuda_runtime.h>
#include <cuda_bf16.h>
#include <mma.h>
#include <math.h>

using namespace nvcuda;

#define NTOK  8192
#define HID   1024
#define INTER 4096
#define NEXP  8
#define NEXPC 7
#define CAP   1024

// ---------------- device scratch (static: no allocations allowed) ----------
__device__ int2   g_e01[NTOK];          // up to 2 non-noop expert ids per token (-1 = none)
__device__ float2 g_w01[NTOK];          // matching weights
__device__ float  g_wn[NTOK];           // noop (expert 7) weight, 0 if not selected
__device__ int    g_list[NEXPC * CAP];  // per-expert kept token ids (padded with 0)
__device__ float  g_wl[NEXPC * CAP];    // per-expert weights (padded with 0)
__device__ float  g_H[(size_t)NEXPC * CAP * INTER]; // relu(X@Wi) scratch, 112MB

// ---------------- router: logits -> softmax -> top2 ------------------------
__global__ __launch_bounds__(256) void router_kernel(const float* __restrict__ x,
                                                     const float* __restrict__ rw,
                                                     const float* __restrict__ rb)
{
    __shared__ __align__(16) float s_rw[NEXP * HID]; // 32KB
    int tid = threadIdx.x;
    for (int i = tid * 4; i < NEXP * HID; i += 256 * 4)
        *(float4*)&s_rw[i] = *(const float4*)&rw[i];
    __syncthreads();

    int lane = tid & 31;
    int warp = tid >> 5;
    int t = blockIdx.x * 8 + warp;

    float acc[NEXP];
#pragma unroll
    for (int e = 0; e < NEXP; e++) acc[e] = 0.f;

    const float4* xr = (const float4*)(x + (size_t)t * HID);
#pragma unroll
    for (int i = 0; i < 8; i++) {
        int k4 = lane + i * 32;
        float4 xv = xr[k4];
#pragma unroll
        for (int e = 0; e < NEXP; e++) {
            float4 wv = *(const float4*)&s_rw[e * HID + k4 * 4];
            acc[e] += xv.x * wv.x + xv.y * wv.y + xv.z * wv.z + xv.w * wv.w;
        }
    }
#pragma unroll
    for (int e = 0; e < NEXP; e++) {
#pragma unroll
        for (int o = 16; o > 0; o >>= 1)
            acc[e] += __shfl_xor_sync(0xffffffffu, acc[e], o);
    }

    if (lane == 0) {
#pragma unroll
        for (int e = 0; e < NEXP; e++) acc[e] += rb[e];
        // top-2 by logit (softmax is monotone); strict > => lowest index wins ties,
        // matching jax.lax.top_k
        int b0 = 0; float v0 = acc[0];
#pragma unroll
        for (int e = 1; e < NEXP; e++) { if (acc[e] > v0) { v0 = acc[e]; b0 = e; } }
        int b1 = -1; float v1 = -3.4e38f;
#pragma unroll
        for (int e = 0; e < NEXP; e++) {
            if (e != b0 && acc[e] > v1) { v1 = acc[e]; b1 = e; }
        }
        float den = 0.f, ex[NEXP];
#pragma unroll
        for (int e = 0; e < NEXP; e++) { ex[e] = expf(acc[e] - v0); den += ex[e]; }
        float w0 = ex[b0] / den;
        float w1 = ex[b1] / den;

        int a0 = -1, a1 = -1; float aw0 = 0.f, aw1 = 0.f, wn = 0.f;
        if (b0 == NEXP - 1) wn = w0; else { a0 = b0; aw0 = w0; }
        if (b1 == NEXP - 1) wn = w1;
        else { if (a0 < 0) { a0 = b1; aw0 = w1; } else { a1 = b1; aw1 = w1; } }

        g_e01[t] = make_int2(a0, a1);
        g_w01[t] = make_float2(aw0, aw1);
        g_wn[t]  = wn;
    }
}

// ---------------- capacity: ordered compaction per expert ------------------
__global__ __launch_bounds__(256) void capacity_kernel()
{
    int e = blockIdx.x;                 // 0..6
    int tid = threadIdx.x;
    int lane = tid & 31, warp = tid >> 5;
    __shared__ int s_base;
    __shared__ int s_wt[8];
    if (tid == 0) s_base = 0;
    __syncthreads();

    for (int c = 0; c < NTOK / 256; c++) {
        int t = c * 256 + tid;
        int2 a = g_e01[t];
        float2 w = g_w01[t];
        int flag = 0; float wt = 0.f;
        if (a.x == e)      { flag = 1; wt = w.x; }
        else if (a.y == e) { flag = 1; wt = w.y; }
        unsigned m = __ballot_sync(0xffffffffu, flag);
        if (lane == 0) s_wt[warp] = __popc(m);
        __syncthreads();
        int base = s_base;
        int off = 0, tot = 0;
#pragma unroll
        for (int i = 0; i < 8; i++) { int v = s_wt[i]; tot += v; if (i < warp) off += v; }
        int pre = __popc(m & ((1u << lane) - 1u));
        int pos = base + off + pre;
        if (flag && pos < CAP) { g_list[e * CAP + pos] = t; g_wl[e * CAP + pos] = wt; }
        __syncthreads();
        if (tid == 0) s_base = base + tot;
    }
    __syncthreads();
    int count = s_base; if (count > CAP) count = CAP;
    for (int i = count + tid; i < CAP; i += 256) { g_list[e * CAP + i] = 0; g_wl[e * CAP + i] = 0.f; }
}

// ---------------- out init: noop passthrough (covers full output) ----------
__global__ __launch_bounds__(256) void init_out_kernel(const float* __restrict__ x,
                                                       float* __restrict__ out)
{
    int i = blockIdx.x * blockDim.x + threadIdx.x;   // float4 index
    float w = g_wn[i >> 8];                          // (i*4)/1024
    float4 v = ((const float4*)x)[i];
    v.x *= w; v.y *= w; v.z *= w; v.w *= w;
    ((float4*)out)[i] = v;
}

// ---------------- GEMM1: H = relu(gather(X) @ Wi) ---------------------------
// 128x128x32 tiles, 8 warps (2x4), warp tile 64x32, wmma tf32 16x16x8.
// Register double-buffer: prefetch next K-slice into regs during MMA.
__global__ __launch_bounds__(256) void gemm1_kernel(const float* __restrict__ x,
                                                    const float* __restrict__ Wi)
{
    int e  = blockIdx.z;
    int bm = blockIdx.y;
    int bn = blockIdx.x;
    __shared__ __align__(16) float As[128][36];
    __shared__ __align__(16) float Bs[32][132];
    int tid = threadIdx.x;
    int warp = tid >> 5;
    int wm = warp & 1;       // 0..1
    int wq = warp >> 1;      // 0..3

    wmma::fragment<wmma::accumulator, 16, 16, 8, float> acc[4][2];
#pragma unroll
    for (int i = 0; i < 4; i++)
#pragma unroll
        for (int j = 0; j < 2; j++) wmma::fill_fragment(acc[i][j], 0.f);

    int arow = tid >> 3;                 // 0..31
    int ac   = (tid & 7) << 2;           // 0..28
    int brow = tid >> 5;                 // derived per-chunk below
    (void)brow;
    int tok[4];
#pragma unroll
    for (int i = 0; i < 4; i++)
        tok[i] = g_list[e * CAP + bm * 128 + i * 32 + arow];

    const float* We = Wi + (size_t)e * HID * INTER;
    int bnc = bn * 128;

    float4 ra[4], rb4[4];
    // prologue: load k0 = 0
#pragma unroll
    for (int i = 0; i < 4; i++)
        ra[i] = *(const float4*)&x[(size_t)tok[i] * HID + ac];
#pragma unroll
    for (int i = 0; i < 4; i++) {
        int id = i * 256 + tid;
        int r = id >> 5, cc = (id & 31) << 2;
        rb4[i] = *(const float4*)&We[(size_t)r * INTER + bnc + cc];
    }
#pragma unroll
    for (int i = 0; i < 4; i++) *(float4*)&As[i * 32 + arow][ac] = ra[i];
#pragma unroll
    for (int i = 0; i < 4; i++) {
        int id = i * 256 + tid;
        int r = id >> 5, cc = (id & 31) << 2;
        *(float4*)&Bs[r][cc] = rb4[i];
    }
    __syncthreads();

    for (int k0 = 0; k0 < HID; k0 += 32) {
        bool has_next = (k0 + 32) < HID;
        if (has_next) {
            int kn = k0 + 32;
#pragma unroll
            for (int i = 0; i < 4; i++)
                ra[i] = *(const float4*)&x[(size_t)tok[i] * HID + kn + ac];
#pragma unroll
            for (int i = 0; i < 4; i++) {
                int id = i * 256 + tid;
                int r = id >> 5, cc = (id & 31) << 2;
                rb4[i] = *(const float4*)&We[(size_t)(kn + r) * INTER + bnc + cc];
            }
        }
#pragma unroll
        for (int kk = 0; kk < 32; kk += 8) {
            wmma::fragment<wmma::matrix_a, 16, 16, 8, wmma::precision::tf32, wmma::row_major> af[4];
            wmma::fragment<wmma::matrix_b, 16, 16, 8, wmma::precision::tf32, wmma::row_major> bf[2];
#pragma unroll
            for (int mi = 0; mi < 4; mi++) {
                wmma::load_matrix_sync(af[mi], &As[wm * 64 + mi * 16][kk], 36);
#pragma unroll
                for (int j = 0; j < af[mi].num_elements; j++)
                    af[mi].x[j] = wmma::__float_to_tf32(af[mi].x[j]);
            }
#pragma unroll
            for (int ni = 0; ni < 2; ni++) {
                wmma::load_matrix_sync(bf[ni], &Bs[kk][wq * 32 + ni * 16], 132);
#pragma unroll
                for (int j = 0; j < bf[ni].num_elements; j++)
                    bf[ni].x[j] = wmma::__float_to_tf32(bf[ni].x[j]);
            }
#pragma unroll
            for (int mi = 0; mi < 4; mi++)
#pragma unroll
                for (int ni = 0; ni < 2; ni++)
                    wmma::mma_sync(acc[mi][ni], af[mi], bf[ni], acc[mi][ni]);
        }
        if (has_next) {
            __syncthreads();   // everyone done reading current tiles
#pragma unroll
            for (int i = 0; i < 4; i++) *(float4*)&As[i * 32 + arow][ac] = ra[i];
#pragma unroll
            for (int i = 0; i < 4; i++) {
                int id = i * 256 + tid;
                int r = id >> 5, cc = (id & 31) << 2;
                *(float4*)&Bs[r][cc] = rb4[i];
            }
            __syncthreads();   // tiles ready
        }
    }

    float* He = g_H + (size_t)e * CAP * INTER;
#pragma unroll
    for (int mi = 0; mi < 4; mi++)
#pragma unroll
        for (int ni = 0; ni < 2; ni++) {
#pragma unroll
            for (int j = 0; j < acc[mi][ni].num_elements; j++)
                acc[mi][ni].x[j] = fmaxf(acc[mi][ni].x[j], 0.f);
            int gm = bm * 128 + wm * 64 + mi * 16;
            int gn = bnc + wq * 32 + ni * 16;
            wmma::store_matrix_sync(&He[(size_t)gm * INTER + gn], acc[mi][ni],
                                    INTER, wmma::mem_row_major);
        }
}

// ---------------- GEMM2: out[tok] += w * (H @ Wo) ---------------------------
__global__ __launch_bounds__(256) void gemm2_kernel(const float* __restrict__ Wo,
                                                    float* __restrict__ out)
{
    int e  = blockIdx.z;
    int bm = blockIdx.y;
    int bn = blockIdx.x;
    __shared__ __align__(16) float As[128][36];
    __shared__ __align__(16) float Bs[32][132];
    int tid = threadIdx.x;
    int lane = tid & 31, warp = tid >> 5;
    int wm = warp & 1;
    int wq = warp >> 1;

    wmma::fragment<wmma::accumulator, 16, 16, 8, float> acc[4][2];
#pragma unroll
    for (int i = 0; i < 4; i++)
#pragma unroll
        for (int j = 0; j < 2; j++) wmma::fill_fragment(acc[i][j], 0.f);

    int arow = tid >> 3;
    int ac   = (tid & 7) << 2;
    const float* Ae = g_H + (size_t)e * CAP * INTER;
    const float* Be = Wo + (size_t)e * INTER * HID;
    int bnc = bn * 128;

    float4 ra[4], rb4[4];
#pragma unroll
    for (int i = 0; i < 4; i++)
        ra[i] = *(const float4*)&Ae[(size_t)(bm * 128 + i * 32 + arow) * INTER + ac];
#pragma unroll
    for (int i = 0; i < 4; i++) {
        int id = i * 256 + tid;
        int r = id >> 5, cc = (id & 31) << 2;
        rb4[i] = *(const float4*)&Be[(size_t)r * HID + bnc + cc];
    }
#pragma unroll
    for (int i = 0; i < 4; i++) *(float4*)&As[i * 32 + arow][ac] = ra[i];
#pragma unroll
    for (int i = 0; i < 4; i++) {
        int id = i * 256 + tid;
        int r = id >> 5, cc = (id & 31) << 2;
        *(float4*)&Bs[r][cc] = rb4[i];
    }
    __syncthreads();

    for (int k0 = 0; k0 < INTER; k0 += 32) {
        bool has_next = (k0 + 32) < INTER;
        if (has_next) {
            int kn = k0 + 32;
#pragma unroll
            for (int i = 0; i < 4; i++)
                ra[i] = *(const float4*)&Ae[(size_t)(bm * 128 + i * 32 + arow) * INTER + kn + ac];
#pragma unroll
            for (int i = 0; i < 4; i++) {
                int id = i * 256 + tid;
                int r = id >> 5, cc = (id & 31) << 2;
                rb4[i] = *(const float4*)&Be[(size_t)(kn + r) * HID + bnc + cc];
            }
        }
#pragma unroll
        for (int kk = 0; kk < 32; kk += 8) {
            wmma::fragment<wmma::matrix_a, 16, 16, 8, wmma::precision::tf32, wmma::row_major> af[4];
            wmma::fragment<wmma::matrix_b, 16, 16, 8, wmma::precision::tf32, wmma::row_major> bf[2];
#pragma unroll
            for (int mi = 0; mi < 4; mi++) {
                wmma::load_matrix_sync(af[mi], &As[wm * 64 + mi * 16][kk], 36);
#pragma unroll
                for (int j = 0; j < af[mi].num_elements; j++)
                    af[mi].x[j] = wmma::__float_to_tf32(af[mi].x[j]);
            }
#pragma unroll
            for (int ni = 0; ni < 2; ni++) {
                wmma::load_matrix_sync(bf[ni], &Bs[kk][wq * 32 + ni * 16], 132);
#pragma unroll
                for (int j = 0; j < bf[ni].num_elements; j++)
                    bf[ni].x[j] = wmma::__float_to_tf32(bf[ni].x[j]);
            }
#pragma unroll
            for (int mi = 0; mi < 4; mi++)
#pragma unroll
                for (int ni = 0; ni < 2; ni++)
                    wmma::mma_sync(acc[mi][ni], af[mi], bf[ni], acc[mi][ni]);
        }
        if (has_next) {
            __syncthreads();
#pragma unroll
            for (int i = 0; i < 4; i++) *(float4*)&As[i * 32 + arow][ac] = ra[i];
#pragma unroll
            for (int i = 0; i < 4; i++) {
                int id = i * 256 + tid;
                int r = id >> 5, cc = (id & 31) << 2;
                *(float4*)&Bs[r][cc] = rb4[i];
            }
            __syncthreads();
        }
    }

    __syncthreads();   // all warps done with As/Bs before reuse as staging

    // epilogue: stage each 16x16 frag into shared (ldm=16: legal multiple of 4,
    // conflict-free), scale by per-row weight, scatter-add into out[token].
    float* patch = (float*)As + warp * 256;
#pragma unroll
    for (int mi = 0; mi < 4; mi++)
#pragma unroll
        for (int ni = 0; ni < 2; ni++) {
            wmma::store_matrix_sync(patch, acc[mi][ni], 16, wmma::mem_row_major);
            __syncwarp();
            int gm0 = bm * 128 + wm * 64 + mi * 16;
            int gn0 = bnc + wq * 32 + ni * 16;
#pragma unroll
            for (int j = 0; j < 8; j++) {
                int idx = lane + j * 32;
                int r = idx >> 4, cc = idx & 15;
                int gm = gm0 + r;
                int tokm = g_list[e * CAP + gm];
                float wt = g_wl[e * CAP + gm];
                atomicAdd(&out[(size_t)tokm * HID + gn0 + cc], wt * patch[r * 16 + cc]);
            }
            __syncwarp();
        }
}

// ---------------- launch ----------------------------------------------------
extern "C" void kernel_launch(void* const* d_in, const int* in_sizes, int n_in,
                              void* d_out, int out_size)
{
    // Defensive: identify inputs by element count (x=8.39M, rw=8192, rb=8,
    // Wi/Wo both 29.36M — keep their relative order). Fall back to positional.
    const float *x = nullptr, *rw = nullptr, *rb = nullptr, *Wi = nullptr, *Wo = nullptr;
    for (int i = 0; i < n_in; i++) {
        long long sz = in_sizes[i];
        const float* p = (const float*)d_in[i];
        if (sz == (long long)NTOK * HID)                { x  = p; }
        else if (sz == NEXP * HID)                      { rw = p; }
        else if (sz == NEXP)                            { rb = p; }
        else if (sz == (long long)NEXPC * HID * INTER)  { if (!Wi) Wi = p; else Wo = p; }
    }
    if (!x || !rw || !rb || !Wi || !Wo) {
        x  = (const float*)d_in[0];
        rw = (const float*)d_in[1];
        rb = (const float*)d_in[2];
        Wi = (const float*)d_in[3];
        Wo = (const float*)d_in[4];
    }
    float* out = (float*)d_out;

    router_kernel<<<NTOK / 8, 256>>>(x, rw, rb);
    capacity_kernel<<<NEXPC, 256>>>();
    init_out_kernel<<<(NTOK * HID / 4) / 256, 256>>>(x, out);
    gemm1_kernel<<<dim3(INTER / 128, CAP / 128, NEXPC), 256>>>(x, Wi);
    gemm2_kernel<<<dim3(HID / 128, CAP / 128, NEXPC), 256>>>(Wo, out);
}

// round 6
// speedup vs baseline: 1.1850x; 1.1850x over previous
#include <cuda_runtime.h>
#include <cuda_bf16.h>
#include <mma.h>
#include <math.h>

using namespace nvcuda;

#define NTOK  8192
#define HID   1024
#define INTER 4096
#define NEXP  8
#define NEXPC 7
#define CAP   1024

#define STAGES 4
#define ASZ (128 * 36)      // floats per A stage (128 rows x 32 cols, pad 36)
#define BSZ (32 * 132)      // floats per B stage (32 rows x 128 cols, pad 132)
#define STAGE_F (ASZ + BSZ) // floats per stage
#define SMEM_BYTES (STAGES * STAGE_F * 4)

// ---------------- device scratch (static: no allocations allowed) ----------
__device__ int2   g_e01[NTOK];
__device__ float2 g_w01[NTOK];
__device__ float  g_wn[NTOK];
__device__ int    g_list[NEXPC * CAP];
__device__ float  g_wl[NEXPC * CAP];
__device__ float  g_H[(size_t)NEXPC * CAP * INTER]; // 112MB scratch

// ---------------- cp.async helpers -----------------------------------------
__device__ __forceinline__ void cp_async16(void* sptr, const void* gptr) {
    unsigned sa = (unsigned)__cvta_generic_to_shared(sptr);
    asm volatile("cp.async.cg.shared.global [%0], [%1], 16;\n" :: "r"(sa), "l"(gptr));
}
__device__ __forceinline__ void cp_commit() {
    asm volatile("cp.async.commit_group;\n");
}
__device__ __forceinline__ void cp_wait2() {
    asm volatile("cp.async.wait_group 2;\n");
}

// ---------------- router: logits -> softmax -> top2 ------------------------
__global__ __launch_bounds__(256) void router_kernel(const float* __restrict__ x,
                                                     const float* __restrict__ rw,
                                                     const float* __restrict__ rb)
{
    __shared__ __align__(16) float s_rw[NEXP * HID];
    int tid = threadIdx.x;
    for (int i = tid * 4; i < NEXP * HID; i += 256 * 4)
        *(float4*)&s_rw[i] = *(const float4*)&rw[i];
    __syncthreads();

    int lane = tid & 31;
    int warp = tid >> 5;
    int t = blockIdx.x * 8 + warp;

    float acc[NEXP];
#pragma unroll
    for (int e = 0; e < NEXP; e++) acc[e] = 0.f;

    const float4* xr = (const float4*)(x + (size_t)t * HID);
#pragma unroll
    for (int i = 0; i < 8; i++) {
        int k4 = lane + i * 32;
        float4 xv = xr[k4];
#pragma unroll
        for (int e = 0; e < NEXP; e++) {
            float4 wv = *(const float4*)&s_rw[e * HID + k4 * 4];
            acc[e] += xv.x * wv.x + xv.y * wv.y + xv.z * wv.z + xv.w * wv.w;
        }
    }
#pragma unroll
    for (int e = 0; e < NEXP; e++) {
#pragma unroll
        for (int o = 16; o > 0; o >>= 1)
            acc[e] += __shfl_xor_sync(0xffffffffu, acc[e], o);
    }

    if (lane == 0) {
#pragma unroll
        for (int e = 0; e < NEXP; e++) acc[e] += rb[e];
        int b0 = 0; float v0 = acc[0];
#pragma unroll
        for (int e = 1; e < NEXP; e++) { if (acc[e] > v0) { v0 = acc[e]; b0 = e; } }
        int b1 = -1; float v1 = -3.4e38f;
#pragma unroll
        for (int e = 0; e < NEXP; e++) {
            if (e != b0 && acc[e] > v1) { v1 = acc[e]; b1 = e; }
        }
        float den = 0.f, ex[NEXP];
#pragma unroll
        for (int e = 0; e < NEXP; e++) { ex[e] = expf(acc[e] - v0); den += ex[e]; }
        float w0 = ex[b0] / den;
        float w1 = ex[b1] / den;

        int a0 = -1, a1 = -1; float aw0 = 0.f, aw1 = 0.f, wn = 0.f;
        if (b0 == NEXP - 1) wn = w0; else { a0 = b0; aw0 = w0; }
        if (b1 == NEXP - 1) wn = w1;
        else { if (a0 < 0) { a0 = b1; aw0 = w1; } else { a1 = b1; aw1 = w1; } }

        g_e01[t] = make_int2(a0, a1);
        g_w01[t] = make_float2(aw0, aw1);
        g_wn[t]  = wn;
    }
}

// ---------------- capacity: ordered compaction per expert ------------------
__global__ __launch_bounds__(256) void capacity_kernel()
{
    int e = blockIdx.x;
    int tid = threadIdx.x;
    int lane = tid & 31, warp = tid >> 5;
    __shared__ int s_base;
    __shared__ int s_wt[8];
    if (tid == 0) s_base = 0;
    __syncthreads();

    for (int c = 0; c < NTOK / 256; c++) {
        int t = c * 256 + tid;
        int2 a = g_e01[t];
        float2 w = g_w01[t];
        int flag = 0; float wt = 0.f;
        if (a.x == e)      { flag = 1; wt = w.x; }
        else if (a.y == e) { flag = 1; wt = w.y; }
        unsigned m = __ballot_sync(0xffffffffu, flag);
        if (lane == 0) s_wt[warp] = __popc(m);
        __syncthreads();
        int base = s_base;
        int off = 0, tot = 0;
#pragma unroll
        for (int i = 0; i < 8; i++) { int v = s_wt[i]; tot += v; if (i < warp) off += v; }
        int pre = __popc(m & ((1u << lane) - 1u));
        int pos = base + off + pre;
        if (flag && pos < CAP) { g_list[e * CAP + pos] = t; g_wl[e * CAP + pos] = wt; }
        __syncthreads();
        if (tid == 0) s_base = base + tot;
    }
    __syncthreads();
    int count = s_base; if (count > CAP) count = CAP;
    for (int i = count + tid; i < CAP; i += 256) { g_list[e * CAP + i] = 0; g_wl[e * CAP + i] = 0.f; }
}

// ---------------- out init: noop passthrough --------------------------------
__global__ __launch_bounds__(256) void init_out_kernel(const float* __restrict__ x,
                                                       float* __restrict__ out)
{
    int i = blockIdx.x * blockDim.x + threadIdx.x;
    float w = g_wn[i >> 8];
    float4 v = ((const float4*)x)[i];
    v.x *= w; v.y *= w; v.z *= w; v.w *= w;
    ((float4*)out)[i] = v;
}

// ---------------- GEMM cores -------------------------------------------------
// 128x128x32 tiles, 8 warps (2x4), warp tile 64x32, wmma tf32 16x16x8.
// 4-stage cp.async pipeline: 3 tiles in flight, one barrier per K-step.

__device__ __forceinline__ void mma_step(float* As, float* Bs, int wm, int wq,
    wmma::fragment<wmma::accumulator, 16, 16, 8, float> (&acc)[4][2])
{
#pragma unroll
    for (int kk = 0; kk < 32; kk += 8) {
        wmma::fragment<wmma::matrix_a, 16, 16, 8, wmma::precision::tf32, wmma::row_major> af[4];
        wmma::fragment<wmma::matrix_b, 16, 16, 8, wmma::precision::tf32, wmma::row_major> bf[2];
#pragma unroll
        for (int mi = 0; mi < 4; mi++) {
            wmma::load_matrix_sync(af[mi], &As[(wm * 64 + mi * 16) * 36 + kk], 36);
#pragma unroll
            for (int j = 0; j < af[mi].num_elements; j++)
                af[mi].x[j] = wmma::__float_to_tf32(af[mi].x[j]);
        }
#pragma unroll
        for (int ni = 0; ni < 2; ni++) {
            wmma::load_matrix_sync(bf[ni], &Bs[kk * 132 + wq * 32 + ni * 16], 132);
#pragma unroll
            for (int j = 0; j < bf[ni].num_elements; j++)
                bf[ni].x[j] = wmma::__float_to_tf32(bf[ni].x[j]);
        }
#pragma unroll
        for (int mi = 0; mi < 4; mi++)
#pragma unroll
            for (int ni = 0; ni < 2; ni++)
                wmma::mma_sync(acc[mi][ni], af[mi], bf[ni], acc[mi][ni]);
    }
}

// ---------------- GEMM1: H = relu(gather(X) @ Wi) ---------------------------
__global__ __launch_bounds__(256, 1) void gemm1_kernel(const float* __restrict__ x,
                                                       const float* __restrict__ Wi)
{
    extern __shared__ __align__(16) float smem[];
    int e  = blockIdx.z;
    int bm = blockIdx.y;
    int bn = blockIdx.x;
    int tid = threadIdx.x;
    int warp = tid >> 5;
    int wm = warp & 1;
    int wq = warp >> 1;

    wmma::fragment<wmma::accumulator, 16, 16, 8, float> acc[4][2];
#pragma unroll
    for (int i = 0; i < 4; i++)
#pragma unroll
        for (int j = 0; j < 2; j++) wmma::fill_fragment(acc[i][j], 0.f);

    int arow = tid >> 3;                 // 0..31
    int ac   = (tid & 7) << 2;           // 0,4,..28
    int tok[4];
#pragma unroll
    for (int i = 0; i < 4; i++)
        tok[i] = g_list[e * CAP + bm * 128 + i * 32 + arow];

    const float* We = Wi + (size_t)e * HID * INTER;
    int bnc = bn * 128;
    const int KT = HID / 32;

    // prologue: issue stages 0..2
#pragma unroll
    for (int s = 0; s < STAGES - 1; s++) {
        float* As = smem + s * STAGE_F;
        float* Bs = As + ASZ;
        int k0 = s * 32;
#pragma unroll
        for (int i = 0; i < 4; i++)
            cp_async16(&As[(i * 32 + arow) * 36 + ac], &x[(size_t)tok[i] * HID + k0 + ac]);
#pragma unroll
        for (int i = 0; i < 4; i++) {
            int id = i * 256 + tid;
            int r = id >> 5, cc = (id & 31) << 2;
            cp_async16(&Bs[r * 132 + cc], &We[(size_t)(k0 + r) * INTER + bnc + cc]);
        }
        cp_commit();
    }

    for (int kt = 0; kt < KT; kt++) {
        cp_wait2();
        __syncthreads();
        // issue tile kt+3 into the stage freed by tile kt-1
        int nt = kt + STAGES - 1;
        if (nt < KT) {
            int st = nt & (STAGES - 1);
            float* As = smem + st * STAGE_F;
            float* Bs = As + ASZ;
            int k0 = nt * 32;
#pragma unroll
            for (int i = 0; i < 4; i++)
                cp_async16(&As[(i * 32 + arow) * 36 + ac], &x[(size_t)tok[i] * HID + k0 + ac]);
#pragma unroll
            for (int i = 0; i < 4; i++) {
                int id = i * 256 + tid;
                int r = id >> 5, cc = (id & 31) << 2;
                cp_async16(&Bs[r * 132 + cc], &We[(size_t)(k0 + r) * INTER + bnc + cc]);
            }
        }
        cp_commit();

        int st = kt & (STAGES - 1);
        mma_step(smem + st * STAGE_F, smem + st * STAGE_F + ASZ, wm, wq, acc);
    }

    float* He = g_H + (size_t)e * CAP * INTER;
#pragma unroll
    for (int mi = 0; mi < 4; mi++)
#pragma unroll
        for (int ni = 0; ni < 2; ni++) {
#pragma unroll
            for (int j = 0; j < acc[mi][ni].num_elements; j++)
                acc[mi][ni].x[j] = fmaxf(acc[mi][ni].x[j], 0.f);
            int gm = bm * 128 + wm * 64 + mi * 16;
            int gn = bnc + wq * 32 + ni * 16;
            wmma::store_matrix_sync(&He[(size_t)gm * INTER + gn], acc[mi][ni],
                                    INTER, wmma::mem_row_major);
        }
}

// ---------------- GEMM2: out[tok] += w * (H @ Wo) ---------------------------
__global__ __launch_bounds__(256, 1) void gemm2_kernel(const float* __restrict__ Wo,
                                                       float* __restrict__ out)
{
    extern __shared__ __align__(16) float smem[];
    int e  = blockIdx.z;
    int bm = blockIdx.y;
    int bn = blockIdx.x;
    int tid = threadIdx.x;
    int lane = tid & 31, warp = tid >> 5;
    int wm = warp & 1;
    int wq = warp >> 1;

    wmma::fragment<wmma::accumulator, 16, 16, 8, float> acc[4][2];
#pragma unroll
    for (int i = 0; i < 4; i++)
#pragma unroll
        for (int j = 0; j < 2; j++) wmma::fill_fragment(acc[i][j], 0.f);

    int arow = tid >> 3;
    int ac   = (tid & 7) << 2;
    const float* Ae = g_H + (size_t)e * CAP * INTER;
    const float* Be = Wo + (size_t)e * INTER * HID;
    int bnc = bn * 128;
    const int KT = INTER / 32;

#pragma unroll
    for (int s = 0; s < STAGES - 1; s++) {
        float* As = smem + s * STAGE_F;
        float* Bs = As + ASZ;
        int k0 = s * 32;
#pragma unroll
        for (int i = 0; i < 4; i++)
            cp_async16(&As[(i * 32 + arow) * 36 + ac],
                       &Ae[(size_t)(bm * 128 + i * 32 + arow) * INTER + k0 + ac]);
#pragma unroll
        for (int i = 0; i < 4; i++) {
            int id = i * 256 + tid;
            int r = id >> 5, cc = (id & 31) << 2;
            cp_async16(&Bs[r * 132 + cc], &Be[(size_t)(k0 + r) * HID + bnc + cc]);
        }
        cp_commit();
    }

    for (int kt = 0; kt < KT; kt++) {
        cp_wait2();
        __syncthreads();
        int nt = kt + STAGES - 1;
        if (nt < KT) {
            int st = nt & (STAGES - 1);
            float* As = smem + st * STAGE_F;
            float* Bs = As + ASZ;
            int k0 = nt * 32;
#pragma unroll
            for (int i = 0; i < 4; i++)
                cp_async16(&As[(i * 32 + arow) * 36 + ac],
                           &Ae[(size_t)(bm * 128 + i * 32 + arow) * INTER + k0 + ac]);
#pragma unroll
            for (int i = 0; i < 4; i++) {
                int id = i * 256 + tid;
                int r = id >> 5, cc = (id & 31) << 2;
                cp_async16(&Bs[r * 132 + cc], &Be[(size_t)(k0 + r) * HID + bnc + cc]);
            }
        }
        cp_commit();

        int st = kt & (STAGES - 1);
        mma_step(smem + st * STAGE_F, smem + st * STAGE_F + ASZ, wm, wq, acc);
    }

    __syncthreads();   // all warps done with smem before reuse as staging

    // epilogue: stage each 16x16 frag into shared (ldm=16), scale by per-row
    // weight, scatter-add into out[token].
    float* patch = smem + warp * 256;
#pragma unroll
    for (int mi = 0; mi < 4; mi++)
#pragma unroll
        for (int ni = 0; ni < 2; ni++) {
            wmma::store_matrix_sync(patch, acc[mi][ni], 16, wmma::mem_row_major);
            __syncwarp();
            int gm0 = bm * 128 + wm * 64 + mi * 16;
            int gn0 = bnc + wq * 32 + ni * 16;
#pragma unroll
            for (int j = 0; j < 8; j++) {
                int idx = lane + j * 32;
                int r = idx >> 4, cc = idx & 15;
                int gm = gm0 + r;
                int tokm = g_list[e * CAP + gm];
                float wt = g_wl[e * CAP + gm];
                atomicAdd(&out[(size_t)tokm * HID + gn0 + cc], wt * patch[r * 16 + cc]);
            }
            __syncwarp();
        }
}

// ---------------- launch ----------------------------------------------------
extern "C" void kernel_launch(void* const* d_in, const int* in_sizes, int n_in,
                              void* d_out, int out_size)
{
    const float *x = nullptr, *rw = nullptr, *rb = nullptr, *Wi = nullptr, *Wo = nullptr;
    for (int i = 0; i < n_in; i++) {
        long long sz = in_sizes[i];
        const float* p = (const float*)d_in[i];
        if (sz == (long long)NTOK * HID)                { x  = p; }
        else if (sz == NEXP * HID)                      { rw = p; }
        else if (sz == NEXP)                            { rb = p; }
        else if (sz == (long long)NEXPC * HID * INTER)  { if (!Wi) Wi = p; else Wo = p; }
    }
    if (!x || !rw || !rb || !Wi || !Wo) {
        x  = (const float*)d_in[0];
        rw = (const float*)d_in[1];
        rb = (const float*)d_in[2];
        Wi = (const float*)d_in[3];
        Wo = (const float*)d_in[4];
    }
    float* out = (float*)d_out;

    static bool attr_done = false;
    if (!attr_done) {
        cudaFuncSetAttribute(gemm1_kernel, cudaFuncAttributeMaxDynamicSharedMemorySize, SMEM_BYTES);
        cudaFuncSetAttribute(gemm2_kernel, cudaFuncAttributeMaxDynamicSharedMemorySize, SMEM_BYTES);
        attr_done = true;
    }

    router_kernel<<<NTOK / 8, 256>>>(x, rw, rb);
    capacity_kernel<<<NEXPC, 256>>>();
    init_out_kernel<<<(NTOK * HID / 4) / 256, 256>>>(x, out);
    gemm1_kernel<<<dim3(INTER / 128, CAP / 128, NEXPC), 256, SMEM_BYTES>>>(x, Wi);
    gemm2_kernel<<<dim3(HID / 128, CAP / 128, NEXPC), 256, SMEM_BYTES>>>(Wo, out);
}

// round 7
// speedup vs baseline: 1.7407x; 1.4689x over previous
#include <cuda_runtime.h>
#include <cuda_bf16.h>
#include <mma.h>
#include <math.h>

using namespace nvcuda;

#define NTOK  8192
#define HID   1024
#define INTER 4096
#define NEXP  8
#define NEXPC 7
#define CAP   1024

#define STAGES 4
#define ASZ (128 * 36)      // floats per A stage (128 rows x 32 cols, pad 36)
#define BSZ (32 * 132)      // floats per B stage (32 rows x 128 cols, pad 132)
#define STAGE_F (ASZ + BSZ) // floats per stage
#define SMEM_BYTES (STAGES * STAGE_F * 4)

// ---------------- device scratch (static: no allocations allowed) ----------
__device__ int2   g_e01[NTOK];
__device__ float2 g_w01[NTOK];
__device__ float  g_wn[NTOK];
__device__ int    g_list[NEXPC * CAP];
__device__ float  g_wl[NEXPC * CAP];
__device__ float  g_H[(size_t)NEXPC * CAP * INTER]; // 112MB scratch

// ---------------- cp.async helpers -----------------------------------------
__device__ __forceinline__ void cp_async16(void* sptr, const void* gptr) {
    unsigned sa = (unsigned)__cvta_generic_to_shared(sptr);
    asm volatile("cp.async.cg.shared.global [%0], [%1], 16;\n" :: "r"(sa), "l"(gptr));
}
__device__ __forceinline__ void cp_commit() {
    asm volatile("cp.async.commit_group;\n");
}
__device__ __forceinline__ void cp_wait2() {
    asm volatile("cp.async.wait_group 2;\n");
}

// ---------------- router: logits -> softmax -> top2 ------------------------
__global__ __launch_bounds__(256) void router_kernel(const float* __restrict__ x,
                                                     const float* __restrict__ rw,
                                                     const float* __restrict__ rb)
{
    __shared__ __align__(16) float s_rw[NEXP * HID];
    int tid = threadIdx.x;
    for (int i = tid * 4; i < NEXP * HID; i += 256 * 4)
        *(float4*)&s_rw[i] = *(const float4*)&rw[i];
    __syncthreads();

    int lane = tid & 31;
    int warp = tid >> 5;
    int t = blockIdx.x * 8 + warp;

    float acc[NEXP];
#pragma unroll
    for (int e = 0; e < NEXP; e++) acc[e] = 0.f;

    const float4* xr = (const float4*)(x + (size_t)t * HID);
#pragma unroll
    for (int i = 0; i < 8; i++) {
        int k4 = lane + i * 32;
        float4 xv = xr[k4];
#pragma unroll
        for (int e = 0; e < NEXP; e++) {
            float4 wv = *(const float4*)&s_rw[e * HID + k4 * 4];
            acc[e] += xv.x * wv.x + xv.y * wv.y + xv.z * wv.z + xv.w * wv.w;
        }
    }
#pragma unroll
    for (int e = 0; e < NEXP; e++) {
#pragma unroll
        for (int o = 16; o > 0; o >>= 1)
            acc[e] += __shfl_xor_sync(0xffffffffu, acc[e], o);
    }

    if (lane == 0) {
#pragma unroll
        for (int e = 0; e < NEXP; e++) acc[e] += rb[e];
        int b0 = 0; float v0 = acc[0];
#pragma unroll
        for (int e = 1; e < NEXP; e++) { if (acc[e] > v0) { v0 = acc[e]; b0 = e; } }
        int b1 = -1; float v1 = -3.4e38f;
#pragma unroll
        for (int e = 0; e < NEXP; e++) {
            if (e != b0 && acc[e] > v1) { v1 = acc[e]; b1 = e; }
        }
        float den = 0.f, ex[NEXP];
#pragma unroll
        for (int e = 0; e < NEXP; e++) { ex[e] = expf(acc[e] - v0); den += ex[e]; }
        float w0 = ex[b0] / den;
        float w1 = ex[b1] / den;

        int a0 = -1, a1 = -1; float aw0 = 0.f, aw1 = 0.f, wn = 0.f;
        if (b0 == NEXP - 1) wn = w0; else { a0 = b0; aw0 = w0; }
        if (b1 == NEXP - 1) wn = w1;
        else { if (a0 < 0) { a0 = b1; aw0 = w1; } else { a1 = b1; aw1 = w1; } }

        g_e01[t] = make_int2(a0, a1);
        g_w01[t] = make_float2(aw0, aw1);
        g_wn[t]  = wn;
    }
}

// ---------------- capacity: ordered compaction per expert ------------------
__global__ __launch_bounds__(256) void capacity_kernel()
{
    int e = blockIdx.x;
    int tid = threadIdx.x;
    int lane = tid & 31, warp = tid >> 5;
    __shared__ int s_base;
    __shared__ int s_wt[8];
    if (tid == 0) s_base = 0;
    __syncthreads();

    for (int c = 0; c < NTOK / 256; c++) {
        int t = c * 256 + tid;
        int2 a = g_e01[t];
        float2 w = g_w01[t];
        int flag = 0; float wt = 0.f;
        if (a.x == e)      { flag = 1; wt = w.x; }
        else if (a.y == e) { flag = 1; wt = w.y; }
        unsigned m = __ballot_sync(0xffffffffu, flag);
        if (lane == 0) s_wt[warp] = __popc(m);
        __syncthreads();
        int base = s_base;
        int off = 0, tot = 0;
#pragma unroll
        for (int i = 0; i < 8; i++) { int v = s_wt[i]; tot += v; if (i < warp) off += v; }
        int pre = __popc(m & ((1u << lane) - 1u));
        int pos = base + off + pre;
        if (flag && pos < CAP) { g_list[e * CAP + pos] = t; g_wl[e * CAP + pos] = wt; }
        __syncthreads();
        if (tid == 0) s_base = base + tot;
    }
    __syncthreads();
    int count = s_base; if (count > CAP) count = CAP;
    for (int i = count + tid; i < CAP; i += 256) { g_list[e * CAP + i] = 0; g_wl[e * CAP + i] = 0.f; }
}

// ---------------- out init: noop passthrough --------------------------------
__global__ __launch_bounds__(256) void init_out_kernel(const float* __restrict__ x,
                                                       float* __restrict__ out)
{
    int i = blockIdx.x * blockDim.x + threadIdx.x;
    float w = g_wn[i >> 8];
    float4 v = ((const float4*)x)[i];
    v.x *= w; v.y *= w; v.z *= w; v.w *= w;
    ((float4*)out)[i] = v;
}

// ---------------- GEMM cores -------------------------------------------------
// 128x128x32 CTA tiles, 512 threads = 16 warps (4x4), warp tile 32x32,
// wmma tf32 16x16x8, 2x2 fragments per warp.
// 4-stage cp.async pipeline: 3 tiles in flight, one barrier per K-step.

__device__ __forceinline__ void mma_step(const float* As, const float* Bs,
    int wr, int wc,
    wmma::fragment<wmma::accumulator, 16, 16, 8, float> (&acc)[2][2])
{
#pragma unroll
    for (int kk = 0; kk < 32; kk += 8) {
        wmma::fragment<wmma::matrix_a, 16, 16, 8, wmma::precision::tf32, wmma::row_major> af[2];
        wmma::fragment<wmma::matrix_b, 16, 16, 8, wmma::precision::tf32, wmma::row_major> bf[2];
#pragma unroll
        for (int mi = 0; mi < 2; mi++) {
            wmma::load_matrix_sync(af[mi], &As[(wr * 32 + mi * 16) * 36 + kk], 36);
#pragma unroll
            for (int j = 0; j < af[mi].num_elements; j++)
                af[mi].x[j] = wmma::__float_to_tf32(af[mi].x[j]);
        }
#pragma unroll
        for (int ni = 0; ni < 2; ni++) {
            wmma::load_matrix_sync(bf[ni], &Bs[kk * 132 + wc * 32 + ni * 16], 132);
#pragma unroll
            for (int j = 0; j < bf[ni].num_elements; j++)
                bf[ni].x[j] = wmma::__float_to_tf32(bf[ni].x[j]);
        }
#pragma unroll
        for (int mi = 0; mi < 2; mi++)
#pragma unroll
            for (int ni = 0; ni < 2; ni++)
                wmma::mma_sync(acc[mi][ni], af[mi], bf[ni], acc[mi][ni]);
    }
}

// ---------------- GEMM1: H = relu(gather(X) @ Wi) ---------------------------
__global__ __launch_bounds__(512, 1) void gemm1_kernel(const float* __restrict__ x,
                                                       const float* __restrict__ Wi)
{
    extern __shared__ __align__(16) float smem[];
    int e  = blockIdx.z;
    int bm = blockIdx.y;
    int bn = blockIdx.x;
    int tid = threadIdx.x;
    int warp = tid >> 5;
    int wr = warp >> 2;      // 0..3 (M)
    int wc = warp & 3;       // 0..3 (N)

    wmma::fragment<wmma::accumulator, 16, 16, 8, float> acc[2][2];
#pragma unroll
    for (int i = 0; i < 2; i++)
#pragma unroll
        for (int j = 0; j < 2; j++) wmma::fill_fragment(acc[i][j], 0.f);

    int arow = tid >> 3;                 // 0..63
    int ac   = (tid & 7) << 2;           // 0,4,..28
    int tok[2];
#pragma unroll
    for (int i = 0; i < 2; i++)
        tok[i] = g_list[e * CAP + bm * 128 + i * 64 + arow];

    const float* We = Wi + (size_t)e * HID * INTER;
    int bnc = bn * 128;
    const int KT = HID / 32;

    // prologue: issue stages 0..2
#pragma unroll
    for (int s = 0; s < STAGES - 1; s++) {
        float* As = smem + s * STAGE_F;
        float* Bs = As + ASZ;
        int k0 = s * 32;
#pragma unroll
        for (int i = 0; i < 2; i++)
            cp_async16(&As[(i * 64 + arow) * 36 + ac], &x[(size_t)tok[i] * HID + k0 + ac]);
#pragma unroll
        for (int i = 0; i < 2; i++) {
            int id = i * 512 + tid;
            int r = id >> 5, cc = (id & 31) << 2;
            cp_async16(&Bs[r * 132 + cc], &We[(size_t)(k0 + r) * INTER + bnc + cc]);
        }
        cp_commit();
    }

    for (int kt = 0; kt < KT; kt++) {
        cp_wait2();
        __syncthreads();
        int nt = kt + STAGES - 1;
        if (nt < KT) {
            int st = nt & (STAGES - 1);
            float* As = smem + st * STAGE_F;
            float* Bs = As + ASZ;
            int k0 = nt * 32;
#pragma unroll
            for (int i = 0; i < 2; i++)
                cp_async16(&As[(i * 64 + arow) * 36 + ac], &x[(size_t)tok[i] * HID + k0 + ac]);
#pragma unroll
            for (int i = 0; i < 2; i++) {
                int id = i * 512 + tid;
                int r = id >> 5, cc = (id & 31) << 2;
                cp_async16(&Bs[r * 132 + cc], &We[(size_t)(k0 + r) * INTER + bnc + cc]);
            }
        }
        cp_commit();

        int st = kt & (STAGES - 1);
        mma_step(smem + st * STAGE_F, smem + st * STAGE_F + ASZ, wr, wc, acc);
    }

    float* He = g_H + (size_t)e * CAP * INTER;
#pragma unroll
    for (int mi = 0; mi < 2; mi++)
#pragma unroll
        for (int ni = 0; ni < 2; ni++) {
#pragma unroll
            for (int j = 0; j < acc[mi][ni].num_elements; j++)
                acc[mi][ni].x[j] = fmaxf(acc[mi][ni].x[j], 0.f);
            int gm = bm * 128 + wr * 32 + mi * 16;
            int gn = bnc + wc * 32 + ni * 16;
            wmma::store_matrix_sync(&He[(size_t)gm * INTER + gn], acc[mi][ni],
                                    INTER, wmma::mem_row_major);
        }
}

// ---------------- GEMM2: out[tok] += w * (H @ Wo) ---------------------------
__global__ __launch_bounds__(512, 1) void gemm2_kernel(const float* __restrict__ Wo,
                                                       float* __restrict__ out)
{
    extern __shared__ __align__(16) float smem[];
    int e  = blockIdx.z;
    int bm = blockIdx.y;
    int bn = blockIdx.x;
    int tid = threadIdx.x;
    int lane = tid & 31, warp = tid >> 5;
    int wr = warp >> 2;
    int wc = warp & 3;

    wmma::fragment<wmma::accumulator, 16, 16, 8, float> acc[2][2];
#pragma unroll
    for (int i = 0; i < 2; i++)
#pragma unroll
        for (int j = 0; j < 2; j++) wmma::fill_fragment(acc[i][j], 0.f);

    int arow = tid >> 3;                 // 0..63
    int ac   = (tid & 7) << 2;
    const float* Ae = g_H + (size_t)e * CAP * INTER;
    const float* Be = Wo + (size_t)e * INTER * HID;
    int bnc = bn * 128;
    const int KT = INTER / 32;

#pragma unroll
    for (int s = 0; s < STAGES - 1; s++) {
        float* As = smem + s * STAGE_F;
        float* Bs = As + ASZ;
        int k0 = s * 32;
#pragma unroll
        for (int i = 0; i < 2; i++)
            cp_async16(&As[(i * 64 + arow) * 36 + ac],
                       &Ae[(size_t)(bm * 128 + i * 64 + arow) * INTER + k0 + ac]);
#pragma unroll
        for (int i = 0; i < 2; i++) {
            int id = i * 512 + tid;
            int r = id >> 5, cc = (id & 31) << 2;
            cp_async16(&Bs[r * 132 + cc], &Be[(size_t)(k0 + r) * HID + bnc + cc]);
        }
        cp_commit();
    }

    for (int kt = 0; kt < KT; kt++) {
        cp_wait2();
        __syncthreads();
        int nt = kt + STAGES - 1;
        if (nt < KT) {
            int st = nt & (STAGES - 1);
            float* As = smem + st * STAGE_F;
            float* Bs = As + ASZ;
            int k0 = nt * 32;
#pragma unroll
            for (int i = 0; i < 2; i++)
                cp_async16(&As[(i * 64 + arow) * 36 + ac],
                           &Ae[(size_t)(bm * 128 + i * 64 + arow) * INTER + k0 + ac]);
#pragma unroll
            for (int i = 0; i < 2; i++) {
                int id = i * 512 + tid;
                int r = id >> 5, cc = (id & 31) << 2;
                cp_async16(&Bs[r * 132 + cc], &Be[(size_t)(k0 + r) * HID + bnc + cc]);
            }
        }
        cp_commit();

        int st = kt & (STAGES - 1);
        mma_step(smem + st * STAGE_F, smem + st * STAGE_F + ASZ, wr, wc, acc);
    }

    __syncthreads();   // all warps done with smem before reuse as staging

    // epilogue: stage each 16x16 frag into shared (ldm=16), scale by per-row
    // weight, scatter-add into out[token].
    float* patch = smem + warp * 256;
#pragma unroll
    for (int mi = 0; mi < 2; mi++)
#pragma unroll
        for (int ni = 0; ni < 2; ni++) {
            wmma::store_matrix_sync(patch, acc[mi][ni], 16, wmma::mem_row_major);
            __syncwarp();
            int gm0 = bm * 128 + wr * 32 + mi * 16;
            int gn0 = bnc + wc * 32 + ni * 16;
#pragma unroll
            for (int j = 0; j < 8; j++) {
                int idx = lane + j * 32;
                int r = idx >> 4, cc = idx & 15;
                int gm = gm0 + r;
                int tokm = g_list[e * CAP + gm];
                float wt = g_wl[e * CAP + gm];
                atomicAdd(&out[(size_t)tokm * HID + gn0 + cc], wt * patch[r * 16 + cc]);
            }
            __syncwarp();
        }
}

// ---------------- launch ----------------------------------------------------
extern "C" void kernel_launch(void* const* d_in, const int* in_sizes, int n_in,
                              void* d_out, int out_size)
{
    const float *x = nullptr, *rw = nullptr, *rb = nullptr, *Wi = nullptr, *Wo = nullptr;
    for (int i = 0; i < n_in; i++) {
        long long sz = in_sizes[i];
        const float* p = (const float*)d_in[i];
        if (sz == (long long)NTOK * HID)                { x  = p; }
        else if (sz == NEXP * HID)                      { rw = p; }
        else if (sz == NEXP)                            { rb = p; }
        else if (sz == (long long)NEXPC * HID * INTER)  { if (!Wi) Wi = p; else Wo = p; }
    }
    if (!x || !rw || !rb || !Wi || !Wo) {
        x  = (const float*)d_in[0];
        rw = (const float*)d_in[1];
        rb = (const float*)d_in[2];
        Wi = (const float*)d_in[3];
        Wo = (const float*)d_in[4];
    }
    float* out = (float*)d_out;

    static bool attr_done = false;
    if (!attr_done) {
        cudaFuncSetAttribute(gemm1_kernel, cudaFuncAttributeMaxDynamicSharedMemorySize, SMEM_BYTES);
        cudaFuncSetAttribute(gemm2_kernel, cudaFuncAttributeMaxDynamicSharedMemorySize, SMEM_BYTES);
        attr_done = true;
    }

    router_kernel<<<NTOK / 8, 256>>>(x, rw, rb);
    capacity_kernel<<<NEXPC, 256>>>();
    init_out_kernel<<<(NTOK * HID / 4) / 256, 256>>>(x, out);
    gemm1_kernel<<<dim3(INTER / 128, CAP / 128, NEXPC), 512, SMEM_BYTES>>>(x, Wi);
    gemm2_kernel<<<dim3(HID / 128, CAP / 128, NEXPC), 512, SMEM_BYTES>>>(Wo, out);
}

// round 8
// speedup vs baseline: 1.7637x; 1.0132x over previous
#include <cuda_runtime.h>
#include <cuda_bf16.h>
#include <mma.h>
#include <math.h>

using namespace nvcuda;

#define NTOK  8192
#define HID   1024
#define INTER 4096
#define NEXP  8
#define NEXPC 7
#define CAP   1024

#define STAGES 4
#define ASZ (128 * 36)      // floats per A stage (128 rows x 32 cols, pad 36)
#define BSZ (32 * 132)      // floats per B stage (32 rows x 128 cols, pad 132)
#define STAGE_F (ASZ + BSZ) // floats per stage
#define SMEM_BYTES (STAGES * STAGE_F * 4)

// ---------------- device scratch (static: no allocations allowed) ----------
__device__ int2   g_e01[NTOK];
__device__ float2 g_w01[NTOK];
__device__ float  g_wn[NTOK];
__device__ int    g_list[NEXPC * CAP];
__device__ float  g_wl[NEXPC * CAP];
__device__ float  g_H[(size_t)NEXPC * CAP * INTER];    // 112MB (tf32-rounded)
__device__ float  g_xr[(size_t)NTOK * HID];            // 32MB  tf32-rounded x
__device__ float  g_Wir[(size_t)NEXPC * HID * INTER];  // 112MB tf32-rounded Wi
__device__ float  g_Wor[(size_t)NEXPC * INTER * HID];  // 112MB tf32-rounded Wo

// ---------------- cp.async helpers -----------------------------------------
__device__ __forceinline__ void cp_async16(void* sptr, const void* gptr) {
    unsigned sa = (unsigned)__cvta_generic_to_shared(sptr);
    asm volatile("cp.async.cg.shared.global [%0], [%1], 16;\n" :: "r"(sa), "l"(gptr));
}
__device__ __forceinline__ void cp_commit() {
    asm volatile("cp.async.commit_group;\n");
}
__device__ __forceinline__ void cp_wait2() {
    asm volatile("cp.async.wait_group 2;\n");
}

// ---------------- tf32 rounding pass ----------------------------------------
__global__ __launch_bounds__(256) void round_tf32_kernel(const float* __restrict__ in,
                                                         float* __restrict__ out)
{
    size_t i = (size_t)blockIdx.x * blockDim.x + threadIdx.x;
    float4 v = ((const float4*)in)[i];
    v.x = wmma::__float_to_tf32(v.x);
    v.y = wmma::__float_to_tf32(v.y);
    v.z = wmma::__float_to_tf32(v.z);
    v.w = wmma::__float_to_tf32(v.w);
    ((float4*)out)[i] = v;
}

// ---------------- router: logits -> softmax -> top2 ------------------------
__global__ __launch_bounds__(256) void router_kernel(const float* __restrict__ x,
                                                     const float* __restrict__ rw,
                                                     const float* __restrict__ rb)
{
    __shared__ __align__(16) float s_rw[NEXP * HID];
    int tid = threadIdx.x;
    for (int i = tid * 4; i < NEXP * HID; i += 256 * 4)
        *(float4*)&s_rw[i] = *(const float4*)&rw[i];
    __syncthreads();

    int lane = tid & 31;
    int warp = tid >> 5;
    int t = blockIdx.x * 8 + warp;

    float acc[NEXP];
#pragma unroll
    for (int e = 0; e < NEXP; e++) acc[e] = 0.f;

    const float4* xr = (const float4*)(x + (size_t)t * HID);
#pragma unroll
    for (int i = 0; i < 8; i++) {
        int k4 = lane + i * 32;
        float4 xv = xr[k4];
#pragma unroll
        for (int e = 0; e < NEXP; e++) {
            float4 wv = *(const float4*)&s_rw[e * HID + k4 * 4];
            acc[e] += xv.x * wv.x + xv.y * wv.y + xv.z * wv.z + xv.w * wv.w;
        }
    }
#pragma unroll
    for (int e = 0; e < NEXP; e++) {
#pragma unroll
        for (int o = 16; o > 0; o >>= 1)
            acc[e] += __shfl_xor_sync(0xffffffffu, acc[e], o);
    }

    if (lane == 0) {
#pragma unroll
        for (int e = 0; e < NEXP; e++) acc[e] += rb[e];
        int b0 = 0; float v0 = acc[0];
#pragma unroll
        for (int e = 1; e < NEXP; e++) { if (acc[e] > v0) { v0 = acc[e]; b0 = e; } }
        int b1 = -1; float v1 = -3.4e38f;
#pragma unroll
        for (int e = 0; e < NEXP; e++) {
            if (e != b0 && acc[e] > v1) { v1 = acc[e]; b1 = e; }
        }
        float den = 0.f, ex[NEXP];
#pragma unroll
        for (int e = 0; e < NEXP; e++) { ex[e] = expf(acc[e] - v0); den += ex[e]; }
        float w0 = ex[b0] / den;
        float w1 = ex[b1] / den;

        int a0 = -1, a1 = -1; float aw0 = 0.f, aw1 = 0.f, wn = 0.f;
        if (b0 == NEXP - 1) wn = w0; else { a0 = b0; aw0 = w0; }
        if (b1 == NEXP - 1) wn = w1;
        else { if (a0 < 0) { a0 = b1; aw0 = w1; } else { a1 = b1; aw1 = w1; } }

        g_e01[t] = make_int2(a0, a1);
        g_w01[t] = make_float2(aw0, aw1);
        g_wn[t]  = wn;
    }
}

// ---------------- capacity: ordered compaction per expert ------------------
__global__ __launch_bounds__(256) void capacity_kernel()
{
    int e = blockIdx.x;
    int tid = threadIdx.x;
    int lane = tid & 31, warp = tid >> 5;
    __shared__ int s_base;
    __shared__ int s_wt[8];
    if (tid == 0) s_base = 0;
    __syncthreads();

    for (int c = 0; c < NTOK / 256; c++) {
        int t = c * 256 + tid;
        int2 a = g_e01[t];
        float2 w = g_w01[t];
        int flag = 0; float wt = 0.f;
        if (a.x == e)      { flag = 1; wt = w.x; }
        else if (a.y == e) { flag = 1; wt = w.y; }
        unsigned m = __ballot_sync(0xffffffffu, flag);
        if (lane == 0) s_wt[warp] = __popc(m);
        __syncthreads();
        int base = s_base;
        int off = 0, tot = 0;
#pragma unroll
        for (int i = 0; i < 8; i++) { int v = s_wt[i]; tot += v; if (i < warp) off += v; }
        int pre = __popc(m & ((1u << lane) - 1u));
        int pos = base + off + pre;
        if (flag && pos < CAP) { g_list[e * CAP + pos] = t; g_wl[e * CAP + pos] = wt; }
        __syncthreads();
        if (tid == 0) s_base = base + tot;
    }
    __syncthreads();
    int count = s_base; if (count > CAP) count = CAP;
    for (int i = count + tid; i < CAP; i += 256) { g_list[e * CAP + i] = 0; g_wl[e * CAP + i] = 0.f; }
}

// ---------------- out init: noop passthrough --------------------------------
__global__ __launch_bounds__(256) void init_out_kernel(const float* __restrict__ x,
                                                       float* __restrict__ out)
{
    int i = blockIdx.x * blockDim.x + threadIdx.x;
    float w = g_wn[i >> 8];
    float4 v = ((const float4*)x)[i];
    v.x *= w; v.y *= w; v.z *= w; v.w *= w;
    ((float4*)out)[i] = v;
}

// ---------------- GEMM cores -------------------------------------------------
// 128x128x32 CTA tiles, 512 threads = 16 warps (4x4), warp tile 32x32,
// wmma tf32 16x16x8, 2x2 fragments per warp. Operands are PRE-ROUNDED to
// tf32 bit patterns, so no cvt in the mainloop (HW truncation is a no-op).
// 4-stage cp.async pipeline: 3 tiles in flight, one barrier per K-step.

__device__ __forceinline__ void mma_step(const float* As, const float* Bs,
    int wr, int wc,
    wmma::fragment<wmma::accumulator, 16, 16, 8, float> (&acc)[2][2])
{
#pragma unroll
    for (int kk = 0; kk < 32; kk += 8) {
        wmma::fragment<wmma::matrix_a, 16, 16, 8, wmma::precision::tf32, wmma::row_major> af[2];
        wmma::fragment<wmma::matrix_b, 16, 16, 8, wmma::precision::tf32, wmma::row_major> bf[2];
#pragma unroll
        for (int mi = 0; mi < 2; mi++)
            wmma::load_matrix_sync(af[mi], &As[(wr * 32 + mi * 16) * 36 + kk], 36);
#pragma unroll
        for (int ni = 0; ni < 2; ni++)
            wmma::load_matrix_sync(bf[ni], &Bs[kk * 132 + wc * 32 + ni * 16], 132);
#pragma unroll
        for (int mi = 0; mi < 2; mi++)
#pragma unroll
            for (int ni = 0; ni < 2; ni++)
                wmma::mma_sync(acc[mi][ni], af[mi], bf[ni], acc[mi][ni]);
    }
}

// ---------------- GEMM1: H = round_tf32(relu(gather(Xr) @ Wir)) -------------
__global__ __launch_bounds__(512, 1) void gemm1_kernel()
{
    extern __shared__ __align__(16) float smem[];
    int e  = blockIdx.z;
    int bm = blockIdx.y;
    int bn = blockIdx.x;
    int tid = threadIdx.x;
    int warp = tid >> 5;
    int wr = warp >> 2;      // 0..3 (M)
    int wc = warp & 3;       // 0..3 (N)

    wmma::fragment<wmma::accumulator, 16, 16, 8, float> acc[2][2];
#pragma unroll
    for (int i = 0; i < 2; i++)
#pragma unroll
        for (int j = 0; j < 2; j++) wmma::fill_fragment(acc[i][j], 0.f);

    int arow = tid >> 3;                 // 0..63
    int ac   = (tid & 7) << 2;           // 0,4,..28
    int tok[2];
#pragma unroll
    for (int i = 0; i < 2; i++)
        tok[i] = g_list[e * CAP + bm * 128 + i * 64 + arow];

    const float* We = g_Wir + (size_t)e * HID * INTER;
    int bnc = bn * 128;
    const int KT = HID / 32;

#pragma unroll
    for (int s = 0; s < STAGES - 1; s++) {
        float* As = smem + s * STAGE_F;
        float* Bs = As + ASZ;
        int k0 = s * 32;
#pragma unroll
        for (int i = 0; i < 2; i++)
            cp_async16(&As[(i * 64 + arow) * 36 + ac], &g_xr[(size_t)tok[i] * HID + k0 + ac]);
#pragma unroll
        for (int i = 0; i < 2; i++) {
            int id = i * 512 + tid;
            int r = id >> 5, cc = (id & 31) << 2;
            cp_async16(&Bs[r * 132 + cc], &We[(size_t)(k0 + r) * INTER + bnc + cc]);
        }
        cp_commit();
    }

    for (int kt = 0; kt < KT; kt++) {
        cp_wait2();
        __syncthreads();
        int nt = kt + STAGES - 1;
        if (nt < KT) {
            int st = nt & (STAGES - 1);
            float* As = smem + st * STAGE_F;
            float* Bs = As + ASZ;
            int k0 = nt * 32;
#pragma unroll
            for (int i = 0; i < 2; i++)
                cp_async16(&As[(i * 64 + arow) * 36 + ac], &g_xr[(size_t)tok[i] * HID + k0 + ac]);
#pragma unroll
            for (int i = 0; i < 2; i++) {
                int id = i * 512 + tid;
                int r = id >> 5, cc = (id & 31) << 2;
                cp_async16(&Bs[r * 132 + cc], &We[(size_t)(k0 + r) * INTER + bnc + cc]);
            }
        }
        cp_commit();

        int st = kt & (STAGES - 1);
        mma_step(smem + st * STAGE_F, smem + st * STAGE_F + ASZ, wr, wc, acc);
    }

    float* He = g_H + (size_t)e * CAP * INTER;
#pragma unroll
    for (int mi = 0; mi < 2; mi++)
#pragma unroll
        for (int ni = 0; ni < 2; ni++) {
#pragma unroll
            for (int j = 0; j < acc[mi][ni].num_elements; j++)
                acc[mi][ni].x[j] = wmma::__float_to_tf32(fmaxf(acc[mi][ni].x[j], 0.f));
            int gm = bm * 128 + wr * 32 + mi * 16;
            int gn = bnc + wc * 32 + ni * 16;
            wmma::store_matrix_sync(&He[(size_t)gm * INTER + gn], acc[mi][ni],
                                    INTER, wmma::mem_row_major);
        }
}

// ---------------- GEMM2: out[tok] += w * (H @ Wor) ---------------------------
__global__ __launch_bounds__(512, 1) void gemm2_kernel(float* __restrict__ out)
{
    extern __shared__ __align__(16) float smem[];
    int e  = blockIdx.z;
    int bm = blockIdx.y;
    int bn = blockIdx.x;
    int tid = threadIdx.x;
    int lane = tid & 31, warp = tid >> 5;
    int wr = warp >> 2;
    int wc = warp & 3;

    wmma::fragment<wmma::accumulator, 16, 16, 8, float> acc[2][2];
#pragma unroll
    for (int i = 0; i < 2; i++)
#pragma unroll
        for (int j = 0; j < 2; j++) wmma::fill_fragment(acc[i][j], 0.f);

    int arow = tid >> 3;                 // 0..63
    int ac   = (tid & 7) << 2;
    const float* Ae = g_H + (size_t)e * CAP * INTER;
    const float* Be = g_Wor + (size_t)e * INTER * HID;
    int bnc = bn * 128;
    const int KT = INTER / 32;

#pragma unroll
    for (int s = 0; s < STAGES - 1; s++) {
        float* As = smem + s * STAGE_F;
        float* Bs = As + ASZ;
        int k0 = s * 32;
#pragma unroll
        for (int i = 0; i < 2; i++)
            cp_async16(&As[(i * 64 + arow) * 36 + ac],
                       &Ae[(size_t)(bm * 128 + i * 64 + arow) * INTER + k0 + ac]);
#pragma unroll
        for (int i = 0; i < 2; i++) {
            int id = i * 512 + tid;
            int r = id >> 5, cc = (id & 31) << 2;
            cp_async16(&Bs[r * 132 + cc], &Be[(size_t)(k0 + r) * HID + bnc + cc]);
        }
        cp_commit();
    }

    for (int kt = 0; kt < KT; kt++) {
        cp_wait2();
        __syncthreads();
        int nt = kt + STAGES - 1;
        if (nt < KT) {
            int st = nt & (STAGES - 1);
            float* As = smem + st * STAGE_F;
            float* Bs = As + ASZ;
            int k0 = nt * 32;
#pragma unroll
            for (int i = 0; i < 2; i++)
                cp_async16(&As[(i * 64 + arow) * 36 + ac],
                           &Ae[(size_t)(bm * 128 + i * 64 + arow) * INTER + k0 + ac]);
#pragma unroll
            for (int i = 0; i < 2; i++) {
                int id = i * 512 + tid;
                int r = id >> 5, cc = (id & 31) << 2;
                cp_async16(&Bs[r * 132 + cc], &Be[(size_t)(k0 + r) * HID + bnc + cc]);
            }
        }
        cp_commit();

        int st = kt & (STAGES - 1);
        mma_step(smem + st * STAGE_F, smem + st * STAGE_F + ASZ, wr, wc, acc);
    }

    __syncthreads();   // all warps done with smem before reuse as staging

    float* patch = smem + warp * 256;
#pragma unroll
    for (int mi = 0; mi < 2; mi++)
#pragma unroll
        for (int ni = 0; ni < 2; ni++) {
            wmma::store_matrix_sync(patch, acc[mi][ni], 16, wmma::mem_row_major);
            __syncwarp();
            int gm0 = bm * 128 + wr * 32 + mi * 16;
            int gn0 = bnc + wc * 32 + ni * 16;
#pragma unroll
            for (int j = 0; j < 8; j++) {
                int idx = lane + j * 32;
                int r = idx >> 4, cc = idx & 15;
                int gm = gm0 + r;
                int tokm = g_list[e * CAP + gm];
                float wt = g_wl[e * CAP + gm];
                atomicAdd(&out[(size_t)tokm * HID + gn0 + cc], wt * patch[r * 16 + cc]);
            }
            __syncwarp();
        }
}

// ---------------- launch ----------------------------------------------------
extern "C" void kernel_launch(void* const* d_in, const int* in_sizes, int n_in,
                              void* d_out, int out_size)
{
    const float *x = nullptr, *rw = nullptr, *rb = nullptr, *Wi = nullptr, *Wo = nullptr;
    for (int i = 0; i < n_in; i++) {
        long long sz = in_sizes[i];
        const float* p = (const float*)d_in[i];
        if (sz == (long long)NTOK * HID)                { x  = p; }
        else if (sz == NEXP * HID)                      { rw = p; }
        else if (sz == NEXP)                            { rb = p; }
        else if (sz == (long long)NEXPC * HID * INTER)  { if (!Wi) Wi = p; else Wo = p; }
    }
    if (!x || !rw || !rb || !Wi || !Wo) {
        x  = (const float*)d_in[0];
        rw = (const float*)d_in[1];
        rb = (const float*)d_in[2];
        Wi = (const float*)d_in[3];
        Wo = (const float*)d_in[4];
    }
    float* out = (float*)d_out;

    static bool attr_done = false;
    if (!attr_done) {
        cudaFuncSetAttribute(gemm1_kernel, cudaFuncAttributeMaxDynamicSharedMemorySize, SMEM_BYTES);
        cudaFuncSetAttribute(gemm2_kernel, cudaFuncAttributeMaxDynamicSharedMemorySize, SMEM_BYTES);
        attr_done = true;
    }

    float* xr_p;  cudaGetSymbolAddress((void**)&xr_p,  g_xr);
    float* wir_p; cudaGetSymbolAddress((void**)&wir_p, g_Wir);
    float* wor_p; cudaGetSymbolAddress((void**)&wor_p, g_Wor);

    router_kernel<<<NTOK / 8, 256>>>(x, rw, rb);
    capacity_kernel<<<NEXPC, 256>>>();
    init_out_kernel<<<(NTOK * HID / 4) / 256, 256>>>(x, out);

    round_tf32_kernel<<<(NTOK * HID / 4) / 256, 256>>>(x, xr_p);
    round_tf32_kernel<<<(NEXPC * HID * INTER / 4) / 256, 256>>>(Wi, wir_p);
    round_tf32_kernel<<<(NEXPC * INTER * HID / 4) / 256, 256>>>(Wo, wor_p);

    gemm1_kernel<<<dim3(INTER / 128, CAP / 128, NEXPC), 512, SMEM_BYTES>>>();
    gemm2_kernel<<<dim3(HID / 128, CAP / 128, NEXPC), 512, SMEM_BYTES>>>(out);
}

// round 13
// speedup vs baseline: 5.8475x; 3.3155x over previous
#include <cuda_runtime.h>
#include <cuda_fp16.h>
#include <stdint.h>
#include <math.h>

#define NTOK  8192
#define HID   1024
#define INTER 4096
#define NEXP  8
#define NEXPC 7
#define CAP   1024

#define STAGES      5
#define STAGE_BYTES 32768           /* A 16KB + B 16KB (fp16, K-chunk 64) */
#define GEMM_SMEM   (STAGES * STAGE_BYTES + 1024)

/* ---------------- device scratch (static: no allocations allowed) -------- */
__device__ int2   g_e01[NTOK];
__device__ float2 g_w01[NTOK];
__device__ float  g_wn[NTOK];
__device__ int    g_list[NEXPC * CAP];
__device__ float  g_wl[NEXPC * CAP];
__device__ __half g_xh[(size_t)NTOK * HID];             /* fp16 x            */
__device__ __half g_Wih[(size_t)NEXPC * INTER * HID];   /* Wi^T [e][n][k]    */
__device__ __half g_Woh[(size_t)NEXPC * HID * INTER];   /* Wo^T [e][n][k]    */
__device__ __half g_Hh[(size_t)NEXPC * CAP * INTER];    /* fp16 H            */

/* ---------------- helpers -------------------------------------------------- */
__device__ __forceinline__ unsigned smem_u32(const void* p) {
    return (unsigned)__cvta_generic_to_shared(p);
}
__device__ __forceinline__ unsigned sw128(unsigned x) { return x ^ ((x >> 3) & 0x70u); }

__device__ __forceinline__ void cp_async16(unsigned sa, const void* g) {
    asm volatile("cp.async.cg.shared.global [%0], [%1], 16;" :: "r"(sa), "l"(g));
}
__device__ __forceinline__ void cp_commit() {
    asm volatile("cp.async.commit_group;");
}
__device__ __forceinline__ void cp_wait_3() {
    asm volatile("cp.async.wait_group 3;");
}

__device__ __forceinline__ void ldm_x4(unsigned* r, unsigned addr) {
    asm volatile("ldmatrix.sync.aligned.m8n8.x4.shared.b16 {%0, %1, %2, %3}, [%4];"
                 : "=r"(r[0]), "=r"(r[1]), "=r"(r[2]), "=r"(r[3]) : "r"(addr));
}
__device__ __forceinline__ void mma16816(float* d, const unsigned* a,
                                         unsigned b0, unsigned b1) {
    asm volatile(
        "mma.sync.aligned.m16n8k16.row.col.f32.f16.f16.f32 "
        "{%0, %1, %2, %3}, {%4, %5, %6, %7}, {%8, %9}, {%0, %1, %2, %3};"
        : "+f"(d[0]), "+f"(d[1]), "+f"(d[2]), "+f"(d[3])
        : "r"(a[0]), "r"(a[1]), "r"(a[2]), "r"(a[3]), "r"(b0), "r"(b1));
}

/* ---------------- router: logits -> softmax -> top2 ---------------------- */
__global__ __launch_bounds__(256) void router_kernel(const float* __restrict__ x,
                                                     const float* __restrict__ rw,
                                                     const float* __restrict__ rb)
{
    __shared__ __align__(16) float s_rw[NEXP * HID];
    int tid = threadIdx.x;
    for (int i = tid * 4; i < NEXP * HID; i += 256 * 4)
        *(float4*)&s_rw[i] = *(const float4*)&rw[i];
    __syncthreads();

    int lane = tid & 31;
    int warp = tid >> 5;
    int t = blockIdx.x * 8 + warp;

    float acc[NEXP];
#pragma unroll
    for (int e = 0; e < NEXP; e++) acc[e] = 0.f;

    const float4* xr = (const float4*)(x + (size_t)t * HID);
#pragma unroll
    for (int i = 0; i < 8; i++) {
        int k4 = lane + i * 32;
        float4 xv = xr[k4];
#pragma unroll
        for (int e = 0; e < NEXP; e++) {
            float4 wv = *(const float4*)&s_rw[e * HID + k4 * 4];
            acc[e] += xv.x * wv.x + xv.y * wv.y + xv.z * wv.z + xv.w * wv.w;
        }
    }
#pragma unroll
    for (int e = 0; e < NEXP; e++) {
#pragma unroll
        for (int o = 16; o > 0; o >>= 1)
            acc[e] += __shfl_xor_sync(0xffffffffu, acc[e], o);
    }

    if (lane == 0) {
#pragma unroll
        for (int e = 0; e < NEXP; e++) acc[e] += rb[e];
        int b0 = 0; float v0 = acc[0];
#pragma unroll
        for (int e = 1; e < NEXP; e++) { if (acc[e] > v0) { v0 = acc[e]; b0 = e; } }
        int b1 = -1; float v1 = -3.4e38f;
#pragma unroll
        for (int e = 0; e < NEXP; e++) {
            if (e != b0 && acc[e] > v1) { v1 = acc[e]; b1 = e; }
        }
        float den = 0.f, ex[NEXP];
#pragma unroll
        for (int e = 0; e < NEXP; e++) { ex[e] = expf(acc[e] - v0); den += ex[e]; }
        float w0 = ex[b0] / den;
        float w1 = ex[b1] / den;

        int a0 = -1, a1 = -1; float aw0 = 0.f, aw1 = 0.f, wn = 0.f;
        if (b0 == NEXP - 1) wn = w0; else { a0 = b0; aw0 = w0; }
        if (b1 == NEXP - 1) wn = w1;
        else { if (a0 < 0) { a0 = b1; aw0 = w1; } else { a1 = b1; aw1 = w1; } }

        g_e01[t] = make_int2(a0, a1);
        g_w01[t] = make_float2(aw0, aw1);
        g_wn[t]  = wn;
    }
}

/* ---------------- capacity: ordered compaction per expert ---------------- */
__global__ __launch_bounds__(256) void capacity_kernel()
{
    int e = blockIdx.x;
    int tid = threadIdx.x;
    int lane = tid & 31, warp = tid >> 5;
    __shared__ int s_base;
    __shared__ int s_wt[8];
    if (tid == 0) s_base = 0;
    __syncthreads();

    for (int c = 0; c < NTOK / 256; c++) {
        int t = c * 256 + tid;
        int2 a = g_e01[t];
        float2 w = g_w01[t];
        int flag = 0; float wt = 0.f;
        if (a.x == e)      { flag = 1; wt = w.x; }
        else if (a.y == e) { flag = 1; wt = w.y; }
        unsigned m = __ballot_sync(0xffffffffu, flag);
        if (lane == 0) s_wt[warp] = __popc(m);
        __syncthreads();
        int base = s_base;
        int off = 0, tot = 0;
#pragma unroll
        for (int i = 0; i < 8; i++) { int v = s_wt[i]; tot += v; if (i < warp) off += v; }
        int pre = __popc(m & ((1u << lane) - 1u));
        int pos = base + off + pre;
        if (flag && pos < CAP) { g_list[e * CAP + pos] = t; g_wl[e * CAP + pos] = wt; }
        __syncthreads();
        if (tid == 0) s_base = base + tot;
    }
    __syncthreads();
    int count = s_base; if (count > CAP) count = CAP;
    for (int i = count + tid; i < CAP; i += 256) { g_list[e * CAP + i] = 0; g_wl[e * CAP + i] = 0.f; }
}

/* ---------------- out init: noop passthrough ------------------------------ */
__global__ __launch_bounds__(256) void init_out_kernel(const float* __restrict__ x,
                                                       float* __restrict__ out)
{
    int i = blockIdx.x * blockDim.x + threadIdx.x;
    float w = g_wn[i >> 8];
    float4 v = ((const float4*)x)[i];
    v.x *= w; v.y *= w; v.z *= w; v.w *= w;
    ((float4*)out)[i] = v;
}

/* ---------------- prepasses ----------------------------------------------- */
__global__ __launch_bounds__(256) void cvt_x_kernel(const float* __restrict__ in)
{
    size_t i = (size_t)blockIdx.x * blockDim.x + threadIdx.x;
    float4 v = ((const float4*)in)[i];
    __half2* p = (__half2*)g_xh;
    p[i * 2 + 0] = __floats2half2_rn(v.x, v.y);
    p[i * 2 + 1] = __floats2half2_rn(v.z, v.w);
}

/* transpose [R][C] f32 -> [C][R] fp16; one 32x32 tile per block */
__global__ __launch_bounds__(256) void transpose_wi_kernel(const float* __restrict__ Wi)
{
    __shared__ float tile[32][33];
    int e = blockIdx.z;
    const float* ip = Wi + (size_t)e * HID * INTER;
    __half* op = g_Wih + (size_t)e * HID * INTER;
    int c0 = blockIdx.x * 32, r0 = blockIdx.y * 32;
    int tx = threadIdx.x & 31, ty = threadIdx.x >> 5;
#pragma unroll
    for (int j = 0; j < 32; j += 8)
        tile[ty + j][tx] = ip[(size_t)(r0 + ty + j) * INTER + c0 + tx];
    __syncthreads();
    int tx2 = (threadIdx.x & 15) * 2, tyw = threadIdx.x >> 4;
#pragma unroll
    for (int j = 0; j < 32; j += 16) {
        int orow = c0 + tyw + j;
        __half2 hv = __floats2half2_rn(tile[tx2][tyw + j], tile[tx2 + 1][tyw + j]);
        *(__half2*)&op[(size_t)orow * HID + r0 + tx2] = hv;
    }
}

__global__ __launch_bounds__(256) void transpose_wo_kernel(const float* __restrict__ Wo)
{
    __shared__ float tile[32][33];
    int e = blockIdx.z;
    const float* ip = Wo + (size_t)e * INTER * HID;
    __half* op = g_Woh + (size_t)e * INTER * HID;
    int c0 = blockIdx.x * 32, r0 = blockIdx.y * 32;
    int tx = threadIdx.x & 31, ty = threadIdx.x >> 5;
#pragma unroll
    for (int j = 0; j < 32; j += 8)
        tile[ty + j][tx] = ip[(size_t)(r0 + ty + j) * HID + c0 + tx];
    __syncthreads();
    int tx2 = (threadIdx.x & 15) * 2, tyw = threadIdx.x >> 4;
#pragma unroll
    for (int j = 0; j < 32; j += 16) {
        int orow = c0 + tyw + j;
        __half2 hv = __floats2half2_rn(tile[tx2][tyw + j], tile[tx2 + 1][tyw + j]);
        *(__half2*)&op[(size_t)orow * INTER + r0 + tx2] = hv;
    }
}

/* ---------------- fp16 GEMM: 128x128 CTA, ldmatrix + mma.m16n8k16 ---------
   8 warps, warp tile 64x32 (4 m16 x 4 n8), K-chunk 64, 5-stage cp.async.
   is_g1 != 0: A = gathered g_xh rows, B = g_Wih; epilogue relu -> g_Hh
   is_g1 == 0: A = g_Hh rows,          B = g_Woh; epilogue weighted atomic -> outp */

#define LOAD_CHUNK(chunk, slot) do {                                              \
    int k0_ = (chunk) * 64;                                                       \
    unsigned sb_ = tile_base + (unsigned)(slot) * STAGE_BYTES;                    \
    for (int t_ = 0; t_ < 4; t_++) {                                              \
        int sid_ = t_ * 256 + tid;                                                \
        int row_ = sid_ >> 3; int seg_ = sid_ & 7;                                \
        size_t r_ = is_g1 ? (size_t)s_tok[row_] : (size_t)(a_row0 + row_);        \
        cp_async16(sb_ + sw128((unsigned)(row_ * 128 + seg_ * 16)),               \
                   Ab + r_ * as_ + k0_ + seg_ * 8);                               \
    }                                                                             \
    for (int t_ = 0; t_ < 4; t_++) {                                              \
        int sid_ = t_ * 256 + tid;                                                \
        int row_ = sid_ >> 3; int seg_ = sid_ & 7;                                \
        cp_async16(sb_ + 16384u + sw128((unsigned)(row_ * 128 + seg_ * 16)),      \
                   Bb + (size_t)(b_row0 + row_) * bs_ + k0_ + seg_ * 8);          \
    }                                                                             \
} while (0)

__global__ __launch_bounds__(256, 1) void gemm_fp16_kernel(int KT, int is_g1,
                                                           float* __restrict__ outp)
{
    extern __shared__ float dsm[];
    __shared__ int s_tok[128];

    int e = blockIdx.z, bm = blockIdx.y, bn = blockIdx.x;
    int tid = threadIdx.x, wid = tid >> 5, lane = tid & 31;

    unsigned tile_base = (smem_u32(dsm) + 1023u) & ~1023u;

    if (is_g1 && tid < 128) s_tok[tid] = g_list[e * CAP + bm * 128 + tid];

    const __half* Ab; size_t as_;
    const __half* Bb; size_t bs_;
    if (is_g1) { Ab = g_xh;                            as_ = HID;
                 Bb = g_Wih + (size_t)e * INTER * HID; bs_ = HID; }
    else       { Ab = g_Hh  + (size_t)e * CAP * INTER; as_ = INTER;
                 Bb = g_Woh + (size_t)e * HID * INTER; bs_ = INTER; }
    int a_row0 = bm * 128, b_row0 = bn * 128;

    __syncthreads();   /* s_tok visible before first gather load */

    /* prologue: chunks 0..3 into slots 0..3 */
    for (int c = 0; c < STAGES - 1; c++) { LOAD_CHUNK(c, c); cp_commit(); }

    /* warp tiling: wr = M half (64), wc = N quarter (32) */
    int wr = wid & 1, wc = wid >> 1;
    int lrow = lane & 15, lkg = lane >> 4;
    int arowb = wr * 64, bcolb = wc * 32;

    float acc[4][4][4];
#pragma unroll
    for (int mi = 0; mi < 4; mi++)
#pragma unroll
        for (int ni = 0; ni < 4; ni++)
#pragma unroll
            for (int q = 0; q < 4; q++) acc[mi][ni][q] = 0.f;

    for (int i = 0; i < KT; i++) {
        cp_wait_3();
        __syncthreads();            /* chunk i resident; slot of chunk i-1 free */

        int n = i + STAGES - 1;
        if (n < KT) { LOAD_CHUNK(n, n % STAGES); }
        cp_commit();

        unsigned sA = tile_base + (unsigned)(i % STAGES) * STAGE_BYTES;
        unsigned sB = sA + 16384u;

#pragma unroll
        for (int k16 = 0; k16 < 4; k16++) {
            unsigned kb = (unsigned)(k16 * 32 + lkg * 16);
            unsigned af[4][4];
#pragma unroll
            for (int mi = 0; mi < 4; mi++)
                ldm_x4(af[mi], sA + sw128((unsigned)((arowb + mi * 16 + lrow) * 128) + kb));
            unsigned bf[2][4];
#pragma unroll
            for (int nb = 0; nb < 2; nb++)
                ldm_x4(bf[nb], sB + sw128((unsigned)((bcolb + nb * 16 + lrow) * 128) + kb));
#pragma unroll
            for (int mi = 0; mi < 4; mi++) {
                mma16816(acc[mi][0], af[mi], bf[0][0], bf[0][2]);
                mma16816(acc[mi][1], af[mi], bf[0][1], bf[0][3]);
                mma16816(acc[mi][2], af[mi], bf[1][0], bf[1][2]);
                mma16816(acc[mi][3], af[mi], bf[1][1], bf[1][3]);
            }
        }
    }

    /* ---------------- epilogue (acc in registers; no sync needed) ----------
       m16n8 D layout: d0,d1 -> (row lane>>2,   col (lane&3)*2, +1)
                       d2,d3 -> (row lane>>2+8, same cols)                   */
    int rbase = (lane >> 2), cpair = (lane & 3) * 2;

    if (is_g1) {
        __half* He = g_Hh + (size_t)e * CAP * INTER;
#pragma unroll
        for (int mi = 0; mi < 4; mi++) {
            int r0 = a_row0 + arowb + mi * 16 + rbase;
#pragma unroll
            for (int ni = 0; ni < 4; ni++) {
                int gc = bn * 128 + bcolb + ni * 8 + cpair;
                float* d = acc[mi][ni];
                __half2 h0 = __floats2half2_rn(fmaxf(d[0], 0.f), fmaxf(d[1], 0.f));
                __half2 h1 = __floats2half2_rn(fmaxf(d[2], 0.f), fmaxf(d[3], 0.f));
                *(__half2*)&He[(size_t)r0 * INTER + gc]       = h0;
                *(__half2*)&He[(size_t)(r0 + 8) * INTER + gc] = h1;
            }
        }
    } else {
#pragma unroll
        for (int mi = 0; mi < 4; mi++) {
            int r0 = a_row0 + arowb + mi * 16 + rbase;
            int tok0 = g_list[e * CAP + r0];
            float wt0 = g_wl[e * CAP + r0];
            int tok1 = g_list[e * CAP + r0 + 8];
            float wt1 = g_wl[e * CAP + r0 + 8];
#pragma unroll
            for (int ni = 0; ni < 4; ni++) {
                int gc = bn * 128 + bcolb + ni * 8 + cpair;
                float* d = acc[mi][ni];
                atomicAdd(&outp[(size_t)tok0 * HID + gc],     wt0 * d[0]);
                atomicAdd(&outp[(size_t)tok0 * HID + gc + 1], wt0 * d[1]);
                atomicAdd(&outp[(size_t)tok1 * HID + gc],     wt1 * d[2]);
                atomicAdd(&outp[(size_t)tok1 * HID + gc + 1], wt1 * d[3]);
            }
        }
    }
}

/* ---------------- launch --------------------------------------------------- */
extern "C" void kernel_launch(void* const* d_in, const int* in_sizes, int n_in,
                              void* d_out, int out_size)
{
    const float *x = 0, *rw = 0, *rb = 0, *Wi = 0, *Wo = 0;
    for (int i = 0; i < n_in; i++) {
        long long sz = in_sizes[i];
        const float* p = (const float*)d_in[i];
        if (sz == (long long)NTOK * HID)                { x  = p; }
        else if (sz == NEXP * HID)                      { rw = p; }
        else if (sz == NEXP)                            { rb = p; }
        else if (sz == (long long)NEXPC * HID * INTER)  { if (!Wi) Wi = p; else Wo = p; }
    }
    if (!x || !rw || !rb || !Wi || !Wo) {
        x  = (const float*)d_in[0];
        rw = (const float*)d_in[1];
        rb = (const float*)d_in[2];
        Wi = (const float*)d_in[3];
        Wo = (const float*)d_in[4];
    }
    float* out = (float*)d_out;

    static bool attr_done = false;
    if (!attr_done) {
        cudaFuncSetAttribute(gemm_fp16_kernel, cudaFuncAttributeMaxDynamicSharedMemorySize,
                             GEMM_SMEM);
        attr_done = true;
    }

    router_kernel<<<NTOK / 8, 256>>>(x, rw, rb);
    capacity_kernel<<<NEXPC, 256>>>();
    init_out_kernel<<<(NTOK * HID / 4) / 256, 256>>>(x, out);

    cvt_x_kernel<<<(NTOK * HID / 4) / 256, 256>>>(x);
    transpose_wi_kernel<<<dim3(INTER / 32, HID / 32, NEXPC), 256>>>(Wi);
    transpose_wo_kernel<<<dim3(HID / 32, INTER / 32, NEXPC), 256>>>(Wo);

    gemm_fp16_kernel<<<dim3(INTER / 128, CAP / 128, NEXPC), 256, GEMM_SMEM>>>(HID / 64, 1, 0);
    gemm_fp16_kernel<<<dim3(HID / 128, CAP / 128, NEXPC), 256, GEMM_SMEM>>>(INTER / 64, 0, out);
}

// round 14
// speedup vs baseline: 6.0962x; 1.0425x over previous
#include <cuda_runtime.h>
#include <cuda_fp16.h>
#include <stdint.h>
#include <math.h>

#define NTOK  8192
#define HID   1024
#define INTER 4096
#define NEXP  8
#define NEXPC 7
#define CAP   1024

#define STAGES      4
#define STAGE_BYTES 49152           /* A 32KB (256 rows) + B 16KB (128 rows) */
#define GEMM_SMEM   (STAGES * STAGE_BYTES + 1024)

/* ---------------- device scratch (static: no allocations allowed) -------- */
__device__ int2   g_e01[NTOK];
__device__ float2 g_w01[NTOK];
__device__ float  g_wn[NTOK];
__device__ int    g_list[NEXPC * CAP];
__device__ float  g_wl[NEXPC * CAP];
__device__ __half g_xh[(size_t)NTOK * HID];             /* fp16 x            */
__device__ __half g_Wih[(size_t)NEXPC * INTER * HID];   /* Wi^T [e][n][k]    */
__device__ __half g_Woh[(size_t)NEXPC * HID * INTER];   /* Wo^T [e][n][k]    */
__device__ __half g_Hh[(size_t)NEXPC * CAP * INTER];    /* fp16 H            */

/* ---------------- helpers -------------------------------------------------- */
__device__ __forceinline__ unsigned smem_u32(const void* p) {
    return (unsigned)__cvta_generic_to_shared(p);
}
__device__ __forceinline__ unsigned sw128(unsigned x) { return x ^ ((x >> 3) & 0x70u); }

__device__ __forceinline__ void cp_async16(unsigned sa, const void* g) {
    asm volatile("cp.async.cg.shared.global [%0], [%1], 16;" :: "r"(sa), "l"(g));
}
__device__ __forceinline__ void cp_commit() {
    asm volatile("cp.async.commit_group;");
}
__device__ __forceinline__ void cp_wait_2() {
    asm volatile("cp.async.wait_group 2;");
}

__device__ __forceinline__ void ldm_x4(unsigned* r, unsigned addr) {
    asm volatile("ldmatrix.sync.aligned.m8n8.x4.shared.b16 {%0, %1, %2, %3}, [%4];"
                 : "=r"(r[0]), "=r"(r[1]), "=r"(r[2]), "=r"(r[3]) : "r"(addr));
}
__device__ __forceinline__ void mma16816(float* d, const unsigned* a,
                                         unsigned b0, unsigned b1) {
    asm volatile(
        "mma.sync.aligned.m16n8k16.row.col.f32.f16.f16.f32 "
        "{%0, %1, %2, %3}, {%4, %5, %6, %7}, {%8, %9}, {%0, %1, %2, %3};"
        : "+f"(d[0]), "+f"(d[1]), "+f"(d[2]), "+f"(d[3])
        : "r"(a[0]), "r"(a[1]), "r"(a[2]), "r"(a[3]), "r"(b0), "r"(b1));
}

/* ---------------- router: logits -> softmax -> top2 ---------------------- */
__global__ __launch_bounds__(256) void router_kernel(const float* __restrict__ x,
                                                     const float* __restrict__ rw,
                                                     const float* __restrict__ rb)
{
    __shared__ __align__(16) float s_rw[NEXP * HID];
    int tid = threadIdx.x;
    for (int i = tid * 4; i < NEXP * HID; i += 256 * 4)
        *(float4*)&s_rw[i] = *(const float4*)&rw[i];
    __syncthreads();

    int lane = tid & 31;
    int warp = tid >> 5;
    int t = blockIdx.x * 8 + warp;

    float acc[NEXP];
#pragma unroll
    for (int e = 0; e < NEXP; e++) acc[e] = 0.f;

    const float4* xr = (const float4*)(x + (size_t)t * HID);
#pragma unroll
    for (int i = 0; i < 8; i++) {
        int k4 = lane + i * 32;
        float4 xv = xr[k4];
#pragma unroll
        for (int e = 0; e < NEXP; e++) {
            float4 wv = *(const float4*)&s_rw[e * HID + k4 * 4];
            acc[e] += xv.x * wv.x + xv.y * wv.y + xv.z * wv.z + xv.w * wv.w;
        }
    }
#pragma unroll
    for (int e = 0; e < NEXP; e++) {
#pragma unroll
        for (int o = 16; o > 0; o >>= 1)
            acc[e] += __shfl_xor_sync(0xffffffffu, acc[e], o);
    }

    if (lane == 0) {
#pragma unroll
        for (int e = 0; e < NEXP; e++) acc[e] += rb[e];
        int b0 = 0; float v0 = acc[0];
#pragma unroll
        for (int e = 1; e < NEXP; e++) { if (acc[e] > v0) { v0 = acc[e]; b0 = e; } }
        int b1 = -1; float v1 = -3.4e38f;
#pragma unroll
        for (int e = 0; e < NEXP; e++) {
            if (e != b0 && acc[e] > v1) { v1 = acc[e]; b1 = e; }
        }
        float den = 0.f, ex[NEXP];
#pragma unroll
        for (int e = 0; e < NEXP; e++) { ex[e] = expf(acc[e] - v0); den += ex[e]; }
        float w0 = ex[b0] / den;
        float w1 = ex[b1] / den;

        int a0 = -1, a1 = -1; float aw0 = 0.f, aw1 = 0.f, wn = 0.f;
        if (b0 == NEXP - 1) wn = w0; else { a0 = b0; aw0 = w0; }
        if (b1 == NEXP - 1) wn = w1;
        else { if (a0 < 0) { a0 = b1; aw0 = w1; } else { a1 = b1; aw1 = w1; } }

        g_e01[t] = make_int2(a0, a1);
        g_w01[t] = make_float2(aw0, aw1);
        g_wn[t]  = wn;
    }
}

/* ---------------- capacity: ordered compaction per expert ---------------- */
__global__ __launch_bounds__(256) void capacity_kernel()
{
    int e = blockIdx.x;
    int tid = threadIdx.x;
    int lane = tid & 31, warp = tid >> 5;
    __shared__ int s_base;
    __shared__ int s_wt[8];
    if (tid == 0) s_base = 0;
    __syncthreads();

    for (int c = 0; c < NTOK / 256; c++) {
        int t = c * 256 + tid;
        int2 a = g_e01[t];
        float2 w = g_w01[t];
        int flag = 0; float wt = 0.f;
        if (a.x == e)      { flag = 1; wt = w.x; }
        else if (a.y == e) { flag = 1; wt = w.y; }
        unsigned m = __ballot_sync(0xffffffffu, flag);
        if (lane == 0) s_wt[warp] = __popc(m);
        __syncthreads();
        int base = s_base;
        int off = 0, tot = 0;
#pragma unroll
        for (int i = 0; i < 8; i++) { int v = s_wt[i]; tot += v; if (i < warp) off += v; }
        int pre = __popc(m & ((1u << lane) - 1u));
        int pos = base + off + pre;
        if (flag && pos < CAP) { g_list[e * CAP + pos] = t; g_wl[e * CAP + pos] = wt; }
        __syncthreads();
        if (tid == 0) s_base = base + tot;
    }
    __syncthreads();
    int count = s_base; if (count > CAP) count = CAP;
    for (int i = count + tid; i < CAP; i += 256) { g_list[e * CAP + i] = 0; g_wl[e * CAP + i] = 0.f; }
}

/* -------- fused: out = w_noop * x ; g_xh = fp16(x) ------------------------ */
__global__ __launch_bounds__(256) void init_cvt_kernel(const float* __restrict__ x,
                                                       float* __restrict__ out)
{
    size_t i = (size_t)blockIdx.x * blockDim.x + threadIdx.x;   /* float4 idx */
    float4 v = ((const float4*)x)[i];
    __half2* p = (__half2*)g_xh;
    p[i * 2 + 0] = __floats2half2_rn(v.x, v.y);
    p[i * 2 + 1] = __floats2half2_rn(v.z, v.w);
    float w = g_wn[i >> 8];
    v.x *= w; v.y *= w; v.z *= w; v.w *= w;
    ((float4*)out)[i] = v;
}

/* transpose [R][C] f32 -> [C][R] fp16; one 32x32 tile per block */
__global__ __launch_bounds__(256) void transpose_wi_kernel(const float* __restrict__ Wi)
{
    __shared__ float tile[32][33];
    int e = blockIdx.z;
    const float* ip = Wi + (size_t)e * HID * INTER;
    __half* op = g_Wih + (size_t)e * HID * INTER;
    int c0 = blockIdx.x * 32, r0 = blockIdx.y * 32;
    int tx = threadIdx.x & 31, ty = threadIdx.x >> 5;
#pragma unroll
    for (int j = 0; j < 32; j += 8)
        tile[ty + j][tx] = ip[(size_t)(r0 + ty + j) * INTER + c0 + tx];
    __syncthreads();
    int tx2 = (threadIdx.x & 15) * 2, tyw = threadIdx.x >> 4;
#pragma unroll
    for (int j = 0; j < 32; j += 16) {
        int orow = c0 + tyw + j;
        __half2 hv = __floats2half2_rn(tile[tx2][tyw + j], tile[tx2 + 1][tyw + j]);
        *(__half2*)&op[(size_t)orow * HID + r0 + tx2] = hv;
    }
}

__global__ __launch_bounds__(256) void transpose_wo_kernel(const float* __restrict__ Wo)
{
    __shared__ float tile[32][33];
    int e = blockIdx.z;
    const float* ip = Wo + (size_t)e * INTER * HID;
    __half* op = g_Woh + (size_t)e * INTER * HID;
    int c0 = blockIdx.x * 32, r0 = blockIdx.y * 32;
    int tx = threadIdx.x & 31, ty = threadIdx.x >> 5;
#pragma unroll
    for (int j = 0; j < 32; j += 8)
        tile[ty + j][tx] = ip[(size_t)(r0 + ty + j) * HID + c0 + tx];
    __syncthreads();
    int tx2 = (threadIdx.x & 15) * 2, tyw = threadIdx.x >> 4;
#pragma unroll
    for (int j = 0; j < 32; j += 16) {
        int orow = c0 + tyw + j;
        __half2 hv = __floats2half2_rn(tile[tx2][tyw + j], tile[tx2 + 1][tyw + j]);
        *(__half2*)&op[(size_t)orow * INTER + r0 + tx2] = hv;
    }
}

/* ---------------- fp16 GEMM: 256x128 CTA, ldmatrix + mma.m16n8k16 ---------
   8 warps as 4(M) x 2(N), warp tile 64x64 (4 m16 x 8 n8), K-chunk 64,
   4-stage cp.async (3 in flight).
   is_g1 != 0: A = gathered g_xh rows, B = g_Wih; epilogue relu -> g_Hh
   is_g1 == 0: A = g_Hh rows,          B = g_Woh; epilogue weighted atomic -> outp */

#define LOAD_CHUNK(chunk, slot) do {                                              \
    int k0_ = (chunk) * 64;                                                       \
    unsigned sb_ = tile_base + (unsigned)(slot) * STAGE_BYTES;                    \
    for (int t_ = 0; t_ < 8; t_++) {      /* A: 2048 segs of 16B (256 rows) */    \
        int sid_ = t_ * 256 + tid;                                                \
        int row_ = sid_ >> 3; int seg_ = sid_ & 7;                                \
        size_t r_ = is_g1 ? (size_t)s_tok[row_] : (size_t)(a_row0 + row_);        \
        cp_async16(sb_ + sw128((unsigned)(row_ * 128 + seg_ * 16)),               \
                   Ab + r_ * as_ + k0_ + seg_ * 8);                               \
    }                                                                             \
    for (int t_ = 0; t_ < 4; t_++) {      /* B: 1024 segs of 16B (128 rows) */    \
        int sid_ = t_ * 256 + tid;                                                \
        int row_ = sid_ >> 3; int seg_ = sid_ & 7;                                \
        cp_async16(sb_ + 32768u + sw128((unsigned)(row_ * 128 + seg_ * 16)),      \
                   Bb + (size_t)(b_row0 + row_) * bs_ + k0_ + seg_ * 8);          \
    }                                                                             \
} while (0)

__global__ __launch_bounds__(256, 1) void gemm_fp16_kernel(int KT, int is_g1,
                                                           float* __restrict__ outp)
{
    extern __shared__ float dsm[];
    __shared__ int s_tok[256];

    int e = blockIdx.z, bm = blockIdx.y, bn = blockIdx.x;
    int tid = threadIdx.x, wid = tid >> 5, lane = tid & 31;

    unsigned tile_base = (smem_u32(dsm) + 1023u) & ~1023u;

    if (is_g1) s_tok[tid] = g_list[e * CAP + bm * 256 + tid];

    const __half* Ab; size_t as_;
    const __half* Bb; size_t bs_;
    if (is_g1) { Ab = g_xh;                            as_ = HID;
                 Bb = g_Wih + (size_t)e * INTER * HID; bs_ = HID; }
    else       { Ab = g_Hh  + (size_t)e * CAP * INTER; as_ = INTER;
                 Bb = g_Woh + (size_t)e * HID * INTER; bs_ = INTER; }
    int a_row0 = bm * 256, b_row0 = bn * 128;

    __syncthreads();   /* s_tok visible before first gather load */

    /* prologue: chunks 0..2 into slots 0..2 */
    for (int c = 0; c < STAGES - 1; c++) { LOAD_CHUNK(c, c); cp_commit(); }

    /* warp tiling: wrm = M quarter (64 rows), wcn = N half (64 cols) */
    int wrm = wid & 3, wcn = wid >> 2;
    int lrow = lane & 15, lkg = lane >> 4;
    int arowb = wrm * 64, bcolb = wcn * 64;

    float acc[4][8][4];
#pragma unroll
    for (int mi = 0; mi < 4; mi++)
#pragma unroll
        for (int ni = 0; ni < 8; ni++)
#pragma unroll
            for (int q = 0; q < 4; q++) acc[mi][ni][q] = 0.f;

    for (int i = 0; i < KT; i++) {
        cp_wait_2();
        __syncthreads();            /* chunk i resident; slot of chunk i-1 free */

        int n = i + STAGES - 1;
        if (n < KT) { LOAD_CHUNK(n, n % STAGES); }
        cp_commit();

        unsigned sA = tile_base + (unsigned)(i % STAGES) * STAGE_BYTES;
        unsigned sB = sA + 32768u;

#pragma unroll
        for (int k16 = 0; k16 < 4; k16++) {
            unsigned kb = (unsigned)(k16 * 32 + lkg * 16);
            unsigned af[4][4];
#pragma unroll
            for (int mi = 0; mi < 4; mi++)
                ldm_x4(af[mi], sA + sw128((unsigned)((arowb + mi * 16 + lrow) * 128) + kb));
            unsigned bf[4][4];
#pragma unroll
            for (int nb = 0; nb < 4; nb++)
                ldm_x4(bf[nb], sB + sw128((unsigned)((bcolb + nb * 16 + lrow) * 128) + kb));
#pragma unroll
            for (int mi = 0; mi < 4; mi++) {
#pragma unroll
                for (int nb = 0; nb < 4; nb++) {
                    mma16816(acc[mi][2 * nb + 0], af[mi], bf[nb][0], bf[nb][2]);
                    mma16816(acc[mi][2 * nb + 1], af[mi], bf[nb][1], bf[nb][3]);
                }
            }
        }
    }

    /* ---------------- epilogue (acc in registers; no sync needed) ----------
       m16n8 D layout: d0,d1 -> (row lane>>2,   col (lane&3)*2, +1)
                       d2,d3 -> (row lane>>2+8, same cols)                   */
    int rbase = (lane >> 2), cpair = (lane & 3) * 2;

    if (is_g1) {
        __half* He = g_Hh + (size_t)e * CAP * INTER;
#pragma unroll
        for (int mi = 0; mi < 4; mi++) {
            int r0 = a_row0 + arowb + mi * 16 + rbase;
#pragma unroll
            for (int ni = 0; ni < 8; ni++) {
                int gc = bn * 128 + bcolb + ni * 8 + cpair;
                float* d = acc[mi][ni];
                __half2 h0 = __floats2half2_rn(fmaxf(d[0], 0.f), fmaxf(d[1], 0.f));
                __half2 h1 = __floats2half2_rn(fmaxf(d[2], 0.f), fmaxf(d[3], 0.f));
                *(__half2*)&He[(size_t)r0 * INTER + gc]       = h0;
                *(__half2*)&He[(size_t)(r0 + 8) * INTER + gc] = h1;
            }
        }
    } else {
#pragma unroll
        for (int mi = 0; mi < 4; mi++) {
            int r0 = a_row0 + arowb + mi * 16 + rbase;
            int tok0 = g_list[e * CAP + r0];
            float wt0 = g_wl[e * CAP + r0];
            int tok1 = g_list[e * CAP + r0 + 8];
            float wt1 = g_wl[e * CAP + r0 + 8];
#pragma unroll
            for (int ni = 0; ni < 8; ni++) {
                int gc = bn * 128 + bcolb + ni * 8 + cpair;
                float* d = acc[mi][ni];
                atomicAdd(&outp[(size_t)tok0 * HID + gc],     wt0 * d[0]);
                atomicAdd(&outp[(size_t)tok0 * HID + gc + 1], wt0 * d[1]);
                atomicAdd(&outp[(size_t)tok1 * HID + gc],     wt1 * d[2]);
                atomicAdd(&outp[(size_t)tok1 * HID + gc + 1], wt1 * d[3]);
            }
        }
    }
}

/* ---------------- launch --------------------------------------------------- */
extern "C" void kernel_launch(void* const* d_in, const int* in_sizes, int n_in,
                              void* d_out, int out_size)
{
    const float *x = 0, *rw = 0, *rb = 0, *Wi = 0, *Wo = 0;
    for (int i = 0; i < n_in; i++) {
        long long sz = in_sizes[i];
        const float* p = (const float*)d_in[i];
        if (sz == (long long)NTOK * HID)                { x  = p; }
        else if (sz == NEXP * HID)                      { rw = p; }
        else if (sz == NEXP)                            { rb = p; }
        else if (sz == (long long)NEXPC * HID * INTER)  { if (!Wi) Wi = p; else Wo = p; }
    }
    if (!x || !rw || !rb || !Wi || !Wo) {
        x  = (const float*)d_in[0];
        rw = (const float*)d_in[1];
        rb = (const float*)d_in[2];
        Wi = (const float*)d_in[3];
        Wo = (const float*)d_in[4];
    }
    float* out = (float*)d_out;

    static bool attr_done = false;
    if (!attr_done) {
        cudaFuncSetAttribute(gemm_fp16_kernel, cudaFuncAttributeMaxDynamicSharedMemorySize,
                             GEMM_SMEM);
        attr_done = true;
    }

    router_kernel<<<NTOK / 8, 256>>>(x, rw, rb);
    capacity_kernel<<<NEXPC, 256>>>();
    init_cvt_kernel<<<(NTOK * HID / 4) / 256, 256>>>(x, out);

    transpose_wi_kernel<<<dim3(INTER / 32, HID / 32, NEXPC), 256>>>(Wi);
    transpose_wo_kernel<<<dim3(HID / 32, INTER / 32, NEXPC), 256>>>(Wo);

    gemm_fp16_kernel<<<dim3(INTER / 128, CAP / 256, NEXPC), 256, GEMM_SMEM>>>(HID / 64, 1, 0);
    gemm_fp16_kernel<<<dim3(HID / 128, CAP / 256, NEXPC), 256, GEMM_SMEM>>>(INTER / 64, 0, out);
}

// round 15
// speedup vs baseline: 6.1168x; 1.0034x over previous
#include <cuda_runtime.h>
#include <cuda_fp16.h>
#include <stdint.h>
#include <math.h>

#define NTOK  8192
#define HID   1024
#define INTER 4096
#define NEXP  8
#define NEXPC 7
#define CAP   1024

#define STAGES      3
#define STAGE_BYTES 32768           /* A 16KB (128 rows) + B 16KB (128 rows) */
#define GEMM_SMEM   (STAGES * STAGE_BYTES + 1024)

/* ---------------- device scratch (static: no allocations allowed) -------- */
__device__ int2   g_e01[NTOK];
__device__ float2 g_w01[NTOK];
__device__ float  g_wn[NTOK];
__device__ int    g_list[NEXPC * CAP];
__device__ float  g_wl[NEXPC * CAP];
__device__ __half g_xh[(size_t)NTOK * HID];             /* fp16 x            */
__device__ __half g_Wih[(size_t)NEXPC * INTER * HID];   /* Wi^T [e][n][k]    */
__device__ __half g_Woh[(size_t)NEXPC * HID * INTER];   /* Wo^T [e][n][k]    */
__device__ __half g_Hh[(size_t)NEXPC * CAP * INTER];    /* fp16 H            */

struct __align__(8) H4 { __half2 a, b; };

/* ---------------- helpers -------------------------------------------------- */
__device__ __forceinline__ unsigned smem_u32(const void* p) {
    return (unsigned)__cvta_generic_to_shared(p);
}
__device__ __forceinline__ unsigned sw128(unsigned x) { return x ^ ((x >> 3) & 0x70u); }

__device__ __forceinline__ void cp_async16(unsigned sa, const void* g) {
    asm volatile("cp.async.cg.shared.global [%0], [%1], 16;" :: "r"(sa), "l"(g));
}
__device__ __forceinline__ void cp_commit() {
    asm volatile("cp.async.commit_group;");
}
__device__ __forceinline__ void cp_wait_1() {
    asm volatile("cp.async.wait_group 1;");
}

__device__ __forceinline__ void ldm_x4(unsigned* r, unsigned addr) {
    asm volatile("ldmatrix.sync.aligned.m8n8.x4.shared.b16 {%0, %1, %2, %3}, [%4];"
                 : "=r"(r[0]), "=r"(r[1]), "=r"(r[2]), "=r"(r[3]) : "r"(addr));
}
__device__ __forceinline__ void mma16816(float* d, const unsigned* a,
                                         unsigned b0, unsigned b1) {
    asm volatile(
        "mma.sync.aligned.m16n8k16.row.col.f32.f16.f16.f32 "
        "{%0, %1, %2, %3}, {%4, %5, %6, %7}, {%8, %9}, {%0, %1, %2, %3};"
        : "+f"(d[0]), "+f"(d[1]), "+f"(d[2]), "+f"(d[3])
        : "r"(a[0]), "r"(a[1]), "r"(a[2]), "r"(a[3]), "r"(b0), "r"(b1));
}

/* ---------------- router: logits -> softmax -> top2 ---------------------- */
__global__ __launch_bounds__(256) void router_kernel(const float* __restrict__ x,
                                                     const float* __restrict__ rw,
                                                     const float* __restrict__ rb)
{
    __shared__ __align__(16) float s_rw[NEXP * HID];
    int tid = threadIdx.x;
    for (int i = tid * 4; i < NEXP * HID; i += 256 * 4)
        *(float4*)&s_rw[i] = *(const float4*)&rw[i];
    __syncthreads();

    int lane = tid & 31;
    int warp = tid >> 5;
    int t = blockIdx.x * 8 + warp;

    float acc[NEXP];
#pragma unroll
    for (int e = 0; e < NEXP; e++) acc[e] = 0.f;

    const float4* xr = (const float4*)(x + (size_t)t * HID);
#pragma unroll
    for (int i = 0; i < 8; i++) {
        int k4 = lane + i * 32;
        float4 xv = xr[k4];
#pragma unroll
        for (int e = 0; e < NEXP; e++) {
            float4 wv = *(const float4*)&s_rw[e * HID + k4 * 4];
            acc[e] += xv.x * wv.x + xv.y * wv.y + xv.z * wv.z + xv.w * wv.w;
        }
    }
#pragma unroll
    for (int e = 0; e < NEXP; e++) {
#pragma unroll
        for (int o = 16; o > 0; o >>= 1)
            acc[e] += __shfl_xor_sync(0xffffffffu, acc[e], o);
    }

    if (lane == 0) {
#pragma unroll
        for (int e = 0; e < NEXP; e++) acc[e] += rb[e];
        int b0 = 0; float v0 = acc[0];
#pragma unroll
        for (int e = 1; e < NEXP; e++) { if (acc[e] > v0) { v0 = acc[e]; b0 = e; } }
        int b1 = -1; float v1 = -3.4e38f;
#pragma unroll
        for (int e = 0; e < NEXP; e++) {
            if (e != b0 && acc[e] > v1) { v1 = acc[e]; b1 = e; }
        }
        float den = 0.f, ex[NEXP];
#pragma unroll
        for (int e = 0; e < NEXP; e++) { ex[e] = expf(acc[e] - v0); den += ex[e]; }
        float w0 = ex[b0] / den;
        float w1 = ex[b1] / den;

        int a0 = -1, a1 = -1; float aw0 = 0.f, aw1 = 0.f, wn = 0.f;
        if (b0 == NEXP - 1) wn = w0; else { a0 = b0; aw0 = w0; }
        if (b1 == NEXP - 1) wn = w1;
        else { if (a0 < 0) { a0 = b1; aw0 = w1; } else { a1 = b1; aw1 = w1; } }

        g_e01[t] = make_int2(a0, a1);
        g_w01[t] = make_float2(aw0, aw1);
        g_wn[t]  = wn;
    }
}

/* ---------------- capacity: ordered compaction per expert ---------------- */
__global__ __launch_bounds__(256) void capacity_kernel()
{
    int e = blockIdx.x;
    int tid = threadIdx.x;
    int lane = tid & 31, warp = tid >> 5;
    __shared__ int s_base;
    __shared__ int s_wt[8];
    if (tid == 0) s_base = 0;
    __syncthreads();

    for (int c = 0; c < NTOK / 256; c++) {
        int t = c * 256 + tid;
        int2 a = g_e01[t];
        float2 w = g_w01[t];
        int flag = 0; float wt = 0.f;
        if (a.x == e)      { flag = 1; wt = w.x; }
        else if (a.y == e) { flag = 1; wt = w.y; }
        unsigned m = __ballot_sync(0xffffffffu, flag);
        if (lane == 0) s_wt[warp] = __popc(m);
        __syncthreads();
        int base = s_base;
        int off = 0, tot = 0;
#pragma unroll
        for (int i = 0; i < 8; i++) { int v = s_wt[i]; tot += v; if (i < warp) off += v; }
        int pre = __popc(m & ((1u << lane) - 1u));
        int pos = base + off + pre;
        if (flag && pos < CAP) { g_list[e * CAP + pos] = t; g_wl[e * CAP + pos] = wt; }
        __syncthreads();
        if (tid == 0) s_base = base + tot;
    }
    __syncthreads();
    int count = s_base; if (count > CAP) count = CAP;
    for (int i = count + tid; i < CAP; i += 256) { g_list[e * CAP + i] = 0; g_wl[e * CAP + i] = 0.f; }
}

/* -------- fused: out = w_noop * x ; g_xh = fp16(x) ------------------------ */
__global__ __launch_bounds__(256) void init_cvt_kernel(const float* __restrict__ x,
                                                       float* __restrict__ out)
{
    size_t i = (size_t)blockIdx.x * blockDim.x + threadIdx.x;   /* float4 idx */
    float4 v = ((const float4*)x)[i];
    __half2* p = (__half2*)g_xh;
    p[i * 2 + 0] = __floats2half2_rn(v.x, v.y);
    p[i * 2 + 1] = __floats2half2_rn(v.z, v.w);
    float w = g_wn[i >> 8];
    v.x *= w; v.y *= w; v.z *= w; v.w *= w;
    ((float4*)out)[i] = v;
}

/* transpose [R][C] f32 -> [C][R] fp16; one 32x32 tile per block.
   Stores are 8B per lane (half4), conflict-free smem reads. */
__global__ __launch_bounds__(256) void transpose_wi_kernel(const float* __restrict__ Wi)
{
    __shared__ float tile[32][33];
    int e = blockIdx.z;
    const float* ip = Wi + (size_t)e * HID * INTER;
    __half* op = g_Wih + (size_t)e * HID * INTER;
    int c0 = blockIdx.x * 32, r0 = blockIdx.y * 32;
    int tid = threadIdx.x;
    int tx = tid & 31, ty = tid >> 5;
#pragma unroll
    for (int j = 0; j < 32; j += 8)
        tile[ty + j][tx] = ip[(size_t)(r0 + ty + j) * INTER + c0 + tx];
    __syncthreads();
    int orow = tid >> 3;            /* 0..31 : output row (input col)  */
    int oc4  = (tid & 7) << 2;      /* 0..28 : output col (input row)  */
    H4 v;
    v.a = __floats2half2_rn(tile[oc4 + 0][orow], tile[oc4 + 1][orow]);
    v.b = __floats2half2_rn(tile[oc4 + 2][orow], tile[oc4 + 3][orow]);
    *(H4*)&op[(size_t)(c0 + orow) * HID + r0 + oc4] = v;
}

__global__ __launch_bounds__(256) void transpose_wo_kernel(const float* __restrict__ Wo)
{
    __shared__ float tile[32][33];
    int e = blockIdx.z;
    const float* ip = Wo + (size_t)e * INTER * HID;
    __half* op = g_Woh + (size_t)e * INTER * HID;
    int c0 = blockIdx.x * 32, r0 = blockIdx.y * 32;
    int tid = threadIdx.x;
    int tx = tid & 31, ty = tid >> 5;
#pragma unroll
    for (int j = 0; j < 32; j += 8)
        tile[ty + j][tx] = ip[(size_t)(r0 + ty + j) * HID + c0 + tx];
    __syncthreads();
    int orow = tid >> 3;
    int oc4  = (tid & 7) << 2;
    H4 v;
    v.a = __floats2half2_rn(tile[oc4 + 0][orow], tile[oc4 + 1][orow]);
    v.b = __floats2half2_rn(tile[oc4 + 2][orow], tile[oc4 + 3][orow]);
    *(H4*)&op[(size_t)(c0 + orow) * INTER + r0 + oc4] = v;
}

/* ---------------- fp16 GEMM: 128x128 CTA, ldmatrix + mma.m16n8k16 ---------
   8 warps as 2(M) x 4(N), warp tile 64x32 (4 m16 x 4 n8), K-chunk 64,
   3-stage cp.async (2 in flight), 2 CTAs/SM (4 warps/SMSP).
   is_g1 != 0: A = gathered g_xh rows, B = g_Wih; epilogue relu -> g_Hh
   is_g1 == 0: A = g_Hh rows,          B = g_Woh; epilogue weighted atomic -> outp */

#define LOAD_CHUNK(chunk, slot) do {                                              \
    int k0_ = (chunk) * 64;                                                       \
    unsigned sb_ = tile_base + (unsigned)(slot) * STAGE_BYTES;                    \
    for (int t_ = 0; t_ < 4; t_++) {      /* A: 1024 segs of 16B (128 rows) */    \
        int sid_ = t_ * 256 + tid;                                                \
        int row_ = sid_ >> 3; int seg_ = sid_ & 7;                                \
        size_t r_ = is_g1 ? (size_t)s_tok[row_] : (size_t)(a_row0 + row_);        \
        cp_async16(sb_ + sw128((unsigned)(row_ * 128 + seg_ * 16)),               \
                   Ab + r_ * as_ + k0_ + seg_ * 8);                               \
    }                                                                             \
    for (int t_ = 0; t_ < 4; t_++) {      /* B: 1024 segs of 16B (128 rows) */    \
        int sid_ = t_ * 256 + tid;                                                \
        int row_ = sid_ >> 3; int seg_ = sid_ & 7;                                \
        cp_async16(sb_ + 16384u + sw128((unsigned)(row_ * 128 + seg_ * 16)),      \
                   Bb + (size_t)(b_row0 + row_) * bs_ + k0_ + seg_ * 8);          \
    }                                                                             \
} while (0)

__global__ __launch_bounds__(256, 2) void gemm_fp16_kernel(int KT, int is_g1,
                                                           float* __restrict__ outp)
{
    extern __shared__ float dsm[];
    __shared__ int s_tok[128];

    int e = blockIdx.z, bm = blockIdx.y, bn = blockIdx.x;
    int tid = threadIdx.x, wid = tid >> 5, lane = tid & 31;

    unsigned tile_base = (smem_u32(dsm) + 1023u) & ~1023u;

    if (is_g1 && tid < 128) s_tok[tid] = g_list[e * CAP + bm * 128 + tid];

    const __half* Ab; size_t as_;
    const __half* Bb; size_t bs_;
    if (is_g1) { Ab = g_xh;                            as_ = HID;
                 Bb = g_Wih + (size_t)e * INTER * HID; bs_ = HID; }
    else       { Ab = g_Hh  + (size_t)e * CAP * INTER; as_ = INTER;
                 Bb = g_Woh + (size_t)e * HID * INTER; bs_ = INTER; }
    int a_row0 = bm * 128, b_row0 = bn * 128;

    __syncthreads();   /* s_tok visible before first gather load */

    /* prologue: chunks 0,1 into slots 0,1 */
    for (int c = 0; c < STAGES - 1; c++) { LOAD_CHUNK(c, c); cp_commit(); }

    /* warp tiling: wr = M half (64 rows), wc = N quarter (32 cols) */
    int wr = wid & 1, wc = wid >> 1;
    int lrow = lane & 15, lkg = lane >> 4;
    int arowb = wr * 64, bcolb = wc * 32;

    float acc[4][4][4];
#pragma unroll
    for (int mi = 0; mi < 4; mi++)
#pragma unroll
        for (int ni = 0; ni < 4; ni++)
#pragma unroll
            for (int q = 0; q < 4; q++) acc[mi][ni][q] = 0.f;

    for (int i = 0; i < KT; i++) {
        cp_wait_1();
        __syncthreads();            /* chunk i resident; slot of chunk i-1 free */

        int n = i + STAGES - 1;
        if (n < KT) { LOAD_CHUNK(n, n % STAGES); }
        cp_commit();

        unsigned sA = tile_base + (unsigned)(i % STAGES) * STAGE_BYTES;
        unsigned sB = sA + 16384u;

#pragma unroll
        for (int k16 = 0; k16 < 4; k16++) {
            unsigned kb = (unsigned)(k16 * 32 + lkg * 16);
            unsigned af[4][4];
#pragma unroll
            for (int mi = 0; mi < 4; mi++)
                ldm_x4(af[mi], sA + sw128((unsigned)((arowb + mi * 16 + lrow) * 128) + kb));
            unsigned bf[2][4];
#pragma unroll
            for (int nb = 0; nb < 2; nb++)
                ldm_x4(bf[nb], sB + sw128((unsigned)((bcolb + nb * 16 + lrow) * 128) + kb));
#pragma unroll
            for (int mi = 0; mi < 4; mi++) {
                mma16816(acc[mi][0], af[mi], bf[0][0], bf[0][2]);
                mma16816(acc[mi][1], af[mi], bf[0][1], bf[0][3]);
                mma16816(acc[mi][2], af[mi], bf[1][0], bf[1][2]);
                mma16816(acc[mi][3], af[mi], bf[1][1], bf[1][3]);
            }
        }
    }

    /* ---------------- epilogue (acc in registers; no sync needed) ----------
       m16n8 D layout: d0,d1 -> (row lane>>2,   col (lane&3)*2, +1)
                       d2,d3 -> (row lane>>2+8, same cols)                   */
    int rbase = (lane >> 2), cpair = (lane & 3) * 2;

    if (is_g1) {
        __half* He = g_Hh + (size_t)e * CAP * INTER;
#pragma unroll
        for (int mi = 0; mi < 4; mi++) {
            int r0 = a_row0 + arowb + mi * 16 + rbase;
#pragma unroll
            for (int ni = 0; ni < 4; ni++) {
                int gc = bn * 128 + bcolb + ni * 8 + cpair;
                float* d = acc[mi][ni];
                __half2 h0 = __floats2half2_rn(fmaxf(d[0], 0.f), fmaxf(d[1], 0.f));
                __half2 h1 = __floats2half2_rn(fmaxf(d[2], 0.f), fmaxf(d[3], 0.f));
                *(__half2*)&He[(size_t)r0 * INTER + gc]       = h0;
                *(__half2*)&He[(size_t)(r0 + 8) * INTER + gc] = h1;
            }
        }
    } else {
#pragma unroll
        for (int mi = 0; mi < 4; mi++) {
            int r0 = a_row0 + arowb + mi * 16 + rbase;
            int tok0 = g_list[e * CAP + r0];
            float wt0 = g_wl[e * CAP + r0];
            int tok1 = g_list[e * CAP + r0 + 8];
            float wt1 = g_wl[e * CAP + r0 + 8];
#pragma unroll
            for (int ni = 0; ni < 4; ni++) {
                int gc = bn * 128 + bcolb + ni * 8 + cpair;
                float* d = acc[mi][ni];
                atomicAdd(&outp[(size_t)tok0 * HID + gc],     wt0 * d[0]);
                atomicAdd(&outp[(size_t)tok0 * HID + gc + 1], wt0 * d[1]);
                atomicAdd(&outp[(size_t)tok1 * HID + gc],     wt1 * d[2]);
                atomicAdd(&outp[(size_t)tok1 * HID + gc + 1], wt1 * d[3]);
            }
        }
    }
}

/* ---------------- launch --------------------------------------------------- */
extern "C" void kernel_launch(void* const* d_in, const int* in_sizes, int n_in,
                              void* d_out, int out_size)
{
    const float *x = 0, *rw = 0, *rb = 0, *Wi = 0, *Wo = 0;
    for (int i = 0; i < n_in; i++) {
        long long sz = in_sizes[i];
        const float* p = (const float*)d_in[i];
        if (sz == (long long)NTOK * HID)                { x  = p; }
        else if (sz == NEXP * HID)                      { rw = p; }
        else if (sz == NEXP)                            { rb = p; }
        else if (sz == (long long)NEXPC * HID * INTER)  { if (!Wi) Wi = p; else Wo = p; }
    }
    if (!x || !rw || !rb || !Wi || !Wo) {
        x  = (const float*)d_in[0];
        rw = (const float*)d_in[1];
        rb = (const float*)d_in[2];
        Wi = (const float*)d_in[3];
        Wo = (const float*)d_in[4];
    }
    float* out = (float*)d_out;

    static bool attr_done = false;
    if (!attr_done) {
        cudaFuncSetAttribute(gemm_fp16_kernel, cudaFuncAttributeMaxDynamicSharedMemorySize,
                             GEMM_SMEM);
        attr_done = true;
    }

    router_kernel<<<NTOK / 8, 256>>>(x, rw, rb);
    capacity_kernel<<<NEXPC, 256>>>();
    init_cvt_kernel<<<(NTOK * HID / 4) / 256, 256>>>(x, out);

    transpose_wi_kernel<<<dim3(INTER / 32, HID / 32, NEXPC), 256>>>(Wi);
    transpose_wo_kernel<<<dim3(HID / 32, INTER / 32, NEXPC), 256>>>(Wo);

    gemm_fp16_kernel<<<dim3(INTER / 128, CAP / 128, NEXPC), 256, GEMM_SMEM>>>(HID / 64, 1, 0);
    gemm_fp16_kernel<<<dim3(HID / 128, CAP / 128, NEXPC), 256, GEMM_SMEM>>>(INTER / 64, 0, out);
}